// round 3
// baseline (speedup 1.0000x reference)
#include <cuda_runtime.h>
#include <cstdint>

#define Bb 512
#define Ss 128
#define Kk 4
#define Hh 128
#define KH 512
#define EPSQ 1e-9f

// ---------------- scratch (device globals; no allocation allowed) ----------
__device__ float g_hat[(size_t)Bb * Kk * Ss * Hh];   // 134 MB: hat[b][k][s][h]
__device__ float g_cw[(size_t)Bb * Kk * Ss];         // 1 MB:  capsule_weight
__device__ float g_dacc[2][Kk * Ss];                 // softmax denom accumulators

// ---------------- f32x2 helpers --------------------------------------------
__device__ __forceinline__ unsigned long long dup2(float x) {
    unsigned long long r;
    asm("mov.b64 %0, {%1, %1};" : "=l"(r) : "f"(x));
    return r;
}
__device__ __forceinline__ void fma2(unsigned long long& acc,
                                     unsigned long long a, unsigned long long b) {
    asm("fma.rn.f32x2 %0, %1, %2, %0;" : "+l"(acc) : "l"(a), "l"(b));
}
__device__ __forceinline__ float2 unpk(unsigned long long v) {
    float2 r;
    asm("mov.b64 {%0, %1}, %2;" : "=f"(r.x), "=f"(r.y) : "l"(v));
    return r;
}

// ---------------- GEMM: hat[b,k,s,h] = sum_h' item[b,s,h'] * w[s, k*H+h, h']
// Per-s GEMM [B x H] @ [H x KH]^T, tile 64x64, k-chunk 64, packed f32x2 math.
#define BM 64
#define BN 64
#define BKc 64

__global__ void __launch_bounds__(256) gemm_kernel(const float* __restrict__ item,
                                                   const float* __restrict__ w) {
    __shared__ unsigned long long As2[BKc][BM];  // {a,a} duplicated, k-major (32KB)
    __shared__ float Bs[BKc][BN];                // k-major (16KB)

    const int s  = blockIdx.z;
    const int b0 = blockIdx.y * BM;
    const int d0 = blockIdx.x * BN;
    const int tid = threadIdx.x;
    const int tx = tid & 15;
    const int ty = tid >> 4;
    const int m0 = tid & 15;
    const int kv = tid >> 4;            // 0..15 -> k = 4*kv .. 4*kv+3

    const float* Ag = item + ((size_t)b0 * Ss + s) * Hh;
    const float* Bg = w    + ((size_t)s * KH + d0) * Hh;

    unsigned long long acc[4][2];
    #pragma unroll
    for (int i = 0; i < 4; i++) { acc[i][0] = 0ull; acc[i][1] = 0ull; }

    #pragma unroll
    for (int kc = 0; kc < Hh; kc += BKc) {
        // stage A duplicated: As2[k][m] = {a, a}
        #pragma unroll
        for (int i = 0; i < 4; i++) {
            int m = m0 + 16 * i;
            float4 v = *(const float4*)(Ag + (size_t)m * (Ss * Hh) + kc + kv * 4);
            As2[kv * 4 + 0][m] = dup2(v.x);
            As2[kv * 4 + 1][m] = dup2(v.y);
            As2[kv * 4 + 2][m] = dup2(v.z);
            As2[kv * 4 + 3][m] = dup2(v.w);
        }
        // stage B transposed to k-major
        #pragma unroll
        for (int i = 0; i < 4; i++) {
            int n = m0 + 16 * i;
            float4 v = *(const float4*)(Bg + (size_t)n * Hh + kc + kv * 4);
            Bs[kv * 4 + 0][n] = v.x; Bs[kv * 4 + 1][n] = v.y;
            Bs[kv * 4 + 2][n] = v.z; Bs[kv * 4 + 3][n] = v.w;
        }
        __syncthreads();

        #pragma unroll
        for (int kk = 0; kk < BKc; kk++) {
            unsigned long long bP0 = *(const unsigned long long*)&Bs[kk][tx * 2];
            unsigned long long bP1 = *(const unsigned long long*)&Bs[kk][tx * 2 + 32];
            #pragma unroll
            for (int i = 0; i < 4; i++) {
                unsigned long long aD = As2[kk][ty * 4 + i];
                fma2(acc[i][0], aD, bP0);
                fma2(acc[i][1], aD, bP1);
            }
        }
        __syncthreads();
    }

    // write: thread owns n = {2tx, 2tx+1} and {2tx+32, 2tx+33}; 64-wide tile
    // never crosses an H=128 boundary.
    const int kcap = d0 >> 7;
    const int h0   = (d0 & 127) + tx * 2;
    #pragma unroll
    for (int i = 0; i < 4; i++) {
        int b = b0 + ty * 4 + i;
        size_t base = (((size_t)b * Kk + kcap) * Ss + s) * Hh;
        float2 u0 = unpk(acc[i][0]);
        float2 u1 = unpk(acc[i][1]);
        *(float2*)&g_hat[base + h0]      = u0;
        *(float2*)&g_hat[base + h0 + 32] = u1;
    }
}

// ---------------- zero the denom accumulators -------------------------------
__global__ void zero_dacc() {
    ((float*)g_dacc)[threadIdx.x] = 0.0f;   // 1024 floats, 1 block of 1024
}

// ---------------- fused routing step for one (b,k) --------------------------
// No hat smem staging: cap-pass streams from DRAM, delta-pass re-reads via L2.
__global__ void __launch_bounds__(256) routing_kernel(const float* __restrict__ mask,
                                                      float* __restrict__ out,
                                                      int iter) {
    __shared__ float sw[Ss];
    __shared__ float cap[Hh];
    __shared__ float red[Hh];

    const int bx  = blockIdx.x;   // b*K + k
    const int b   = bx >> 2;
    const int k   = bx & 3;
    const int tid = threadIdx.x;
    const float* __restrict__ hp = g_hat + (size_t)bx * (Ss * Hh);

    // ---- sw[s]
    if (tid < Ss) {
        float m = mask[b * Ss + tid];
        float v;
        if (iter == 0) {
            v = 1.0f / (float)Bb;                       // softmax over b of zeros
        } else {
            float e = __expf(g_cw[(size_t)bx * Ss + tid]);
            v = e / g_dacc[iter - 1][k * Ss + tid];
        }
        sw[tid] = (m == 0.0f) ? 0.0f : v;
    }
    __syncthreads();

    // ---- cap[h] = sum_s sw[s] * hat[s][h]  (two s-halves across 256 threads)
    {
        int h = tid & 127, half = tid >> 7;
        const float* p = hp + half * 64 * Hh + h;
        float acc = 0.0f;
        #pragma unroll 16
        for (int s = 0; s < 64; s++)
            acc += sw[half * 64 + s] * p[(size_t)s * Hh];
        if (half) red[h] = acc;
        __syncthreads();
        if (!half) cap[h] = acc + red[h];
    }
    __syncthreads();

    // ---- squash
    {
        float v = (tid < Hh) ? cap[tid] * cap[tid] : 0.0f;
        #pragma unroll
        for (int off = 16; off; off >>= 1)
            v += __shfl_down_sync(0xffffffffu, v, off);
        if ((tid & 31) == 0) red[tid >> 5] = v;
        __syncthreads();
        if (tid == 0) {
            float n = 0.0f;
            #pragma unroll
            for (int i = 0; i < 8; i++) n += red[i];
            red[8] = n / (1.0f + n) * rsqrtf(n + EPSQ);
        }
        __syncthreads();
        float f = red[8];
        if (tid < Hh) cap[tid] *= f;
    }
    __syncthreads();

    if (iter < 2) {
        // ---- delta[s] = hat[s][:] . cap ; update cw ; accumulate exp(cw)
        int warp = tid >> 5, lane = tid & 31;
        for (int s = warp; s < Ss; s += 8) {
            const float* q = hp + (size_t)s * Hh;
            float d = 0.0f;
            #pragma unroll
            for (int i = 0; i < 4; i++)
                d += q[lane + 32 * i] * cap[lane + 32 * i];
            #pragma unroll
            for (int off = 16; off; off >>= 1)
                d += __shfl_down_sync(0xffffffffu, d, off);
            if (lane == 0) {
                size_t idx = (size_t)bx * Ss + s;
                float nc = (iter == 0) ? d : (g_cw[idx] + d);
                g_cw[idx] = nc;
                atomicAdd(&g_dacc[iter][k * Ss + s], __expf(nc));
            }
        }
    } else {
        if (tid < Hh) out[(size_t)bx * Hh + tid] = cap[tid];
    }
}

// ---------------- launch -----------------------------------------------------
extern "C" void kernel_launch(void* const* d_in, const int* in_sizes, int n_in,
                              void* d_out, int out_size) {
    const float* item = (const float*)d_in[0];   // [B,S,H]
    const float* mask = (const float*)d_in[1];   // [B,S]
    const float* w    = (const float*)d_in[2];   // [1,S,K*H,H]
    float* out = (float*)d_out;                  // [B,K,H]

    zero_dacc<<<1, 1024>>>();

    dim3 gg(KH / BN, Bb / BM, Ss);
    gemm_kernel<<<gg, 256>>>(item, w);

    routing_kernel<<<Bb * Kk, 256>>>(mask, out, 0);
    routing_kernel<<<Bb * Kk, 256>>>(mask, out, 1);
    routing_kernel<<<Bb * Kk, 256>>>(mask, out, 2);
}

// round 4
// speedup vs baseline: 1.3275x; 1.3275x over previous
#include <cuda_runtime.h>
#include <cstdint>

#define Bb 512
#define Ss 128
#define Kk 4
#define Hh 128
#define KH 512
#define EPSQ 1e-9f

typedef unsigned long long u64;

// ---------------- scratch (device globals; no allocation allowed) ----------
__device__ float g_hat[(size_t)Bb * Kk * Ss * Hh];   // 134 MB: hat[b][k][s][h]
__device__ float g_cw[(size_t)Bb * Kk * Ss];         // capsule_weight
__device__ float g_dacc[2][Kk * Ss];                 // softmax denom accumulators

// ---------------- f32x2 helpers --------------------------------------------
__device__ __forceinline__ u64 dup2(float x) {
    u64 r;
    asm("mov.b64 %0, {%1, %1};" : "=l"(r) : "f"(x));
    return r;
}
__device__ __forceinline__ void fma2(u64& acc, u64 a, u64 b) {
    asm("fma.rn.f32x2 %0, %1, %2, %0;" : "+l"(acc) : "l"(a), "l"(b));
}

// ---------------- mbarrier / bulk-copy helpers ------------------------------
__device__ __forceinline__ void mbar_init(uint32_t mbar, uint32_t cnt) {
    asm volatile("mbarrier.init.shared.b64 [%0], %1;" :: "r"(mbar), "r"(cnt) : "memory");
}
__device__ __forceinline__ void mbar_expect_tx(uint32_t mbar, uint32_t bytes) {
    asm volatile("mbarrier.arrive.expect_tx.shared.b64 _, [%0], %1;"
                 :: "r"(mbar), "r"(bytes) : "memory");
}
__device__ __forceinline__ void bulk_g2s(uint32_t dst, const void* src,
                                         uint32_t bytes, uint32_t mbar) {
    asm volatile(
        "cp.async.bulk.shared::cluster.global.mbarrier::complete_tx::bytes "
        "[%0], [%1], %2, [%3];"
        :: "r"(dst), "l"(src), "r"(bytes), "r"(mbar) : "memory");
}
__device__ __forceinline__ void mbar_wait(uint32_t mbar, uint32_t phase) {
    asm volatile(
        "{\n\t.reg .pred P;\n\t"
        "WL%=:\n\t"
        "mbarrier.try_wait.parity.shared.b64 P, [%0], %1;\n\t"
        "@!P bra WL%=;\n\t}"
        :: "r"(mbar), "r"(phase) : "memory");
}

// ---------------- GEMM: hat[b,k,s,h] = sum_h' item[b,s,h'] * w[s, k*H+h, h']
// 128x128 tile, BK=64, 128 threads, 16x8 per thread, packed f32x2.
#define GBM 128
#define GBN 128
#define GBK 64

__global__ void __launch_bounds__(128) gemm_kernel(const float* __restrict__ item,
                                                   const float* __restrict__ w) {
    extern __shared__ float sm[];
    float* As = sm;                 // [GBK][GBM], xor-swizzled columns (32KB)
    float* Bs = sm + GBK * GBM;     // [GBK][GBN]                       (32KB)

    const int s  = blockIdx.z;
    const int b0 = blockIdx.y * GBM;
    const int d0 = blockIdx.x * GBN;
    const int tid  = threadIdx.x;
    const int warp = tid >> 5, lane = tid & 31;
    const int wm = warp >> 1, wn = warp & 1;
    const int tm = lane >> 3, tn = lane & 7;
    const int m_base = wm * 64 + tm * 16;
    const int n_base = wn * 64 + tn * 8;

    // loader mapping: f4 = which float4 of the 64-float row segment, r0 = row
    const int f4  = tid & 15;
    const int r0  = tid >> 4;           // 0..7
    const int xsw = (f4 & 7) << 2;      // store-side xor swizzle (matches k>>2)

    const float* Ag = item + ((size_t)b0 * Ss + s) * Hh + f4 * 4;
    const float* Bg = w    + ((size_t)s * KH + d0) * Hh + f4 * 4;

    u64 acc[16][4];
    #pragma unroll
    for (int i = 0; i < 16; i++)
        #pragma unroll
        for (int j = 0; j < 4; j++) acc[i][j] = 0ull;

    for (int kc = 0; kc < Hh; kc += GBK) {
        // ---- stage tiles, k-major, xor-swizzled (2-way STS conflicts)
        #pragma unroll
        for (int p = 0; p < 16; p++) {
            int m = r0 + p * 8;
            int col = m ^ xsw;
            float4 va = *(const float4*)(Ag + (size_t)m * (Ss * Hh) + kc);
            As[(f4 * 4 + 0) * GBM + col] = va.x;
            As[(f4 * 4 + 1) * GBM + col] = va.y;
            As[(f4 * 4 + 2) * GBM + col] = va.z;
            As[(f4 * 4 + 3) * GBM + col] = va.w;
            float4 vb = *(const float4*)(Bg + (size_t)m * Hh + kc);
            Bs[(f4 * 4 + 0) * GBN + col] = vb.x;
            Bs[(f4 * 4 + 1) * GBN + col] = vb.y;
            Bs[(f4 * 4 + 2) * GBN + col] = vb.z;
            Bs[(f4 * 4 + 3) * GBN + col] = vb.w;
        }
        __syncthreads();

        #pragma unroll 2
        for (int k = 0; k < GBK; k++) {
            const int x = ((k >> 2) & 7) << 2;
            const float* ar = As + k * GBM;
            const float* br = Bs + k * GBN;
            float4 a0 = *(const float4*)(ar + ((m_base +  0) ^ x));
            float4 a1 = *(const float4*)(ar + ((m_base +  4) ^ x));
            float4 a2 = *(const float4*)(ar + ((m_base +  8) ^ x));
            float4 a3 = *(const float4*)(ar + ((m_base + 12) ^ x));
            ulonglong2 bb0 = *(const ulonglong2*)(br + ((n_base + 0) ^ x));
            ulonglong2 bb1 = *(const ulonglong2*)(br + ((n_base + 4) ^ x));
            u64 bp[4] = { bb0.x, bb0.y, bb1.x, bb1.y };
            float av[16] = { a0.x, a0.y, a0.z, a0.w, a1.x, a1.y, a1.z, a1.w,
                             a2.x, a2.y, a2.z, a2.w, a3.x, a3.y, a3.z, a3.w };
            #pragma unroll
            for (int i = 0; i < 16; i++) {
                u64 ad = dup2(av[i]);
                fma2(acc[i][0], ad, bp[0]);
                fma2(acc[i][1], ad, bp[1]);
                fma2(acc[i][2], ad, bp[2]);
                fma2(acc[i][3], ad, bp[3]);
            }
        }
        __syncthreads();
    }

    // ---- epilogue: BN=128 == H, so d0 selects the capsule directly
    const int kcap = d0 >> 7;
    #pragma unroll
    for (int i = 0; i < 16; i++) {
        int b = b0 + m_base + i;
        size_t base = (((size_t)b * Kk + kcap) * Ss + s) * Hh + n_base;
        *(ulonglong2*)&g_hat[base]     = make_ulonglong2(acc[i][0], acc[i][1]);
        *(ulonglong2*)&g_hat[base + 4] = make_ulonglong2(acc[i][2], acc[i][3]);
    }
}

// ---------------- zero the denom accumulators -------------------------------
__global__ void zero_dacc() {
    ((float*)g_dacc)[threadIdx.x] = 0.0f;   // 1024 floats
}

// ---------------- fused routing step for one (b,k) --------------------------
// hat tile streamed into smem via 4 chunked cp.async.bulk; cap-pass consumes
// chunks as they land; delta-pass reads smem.
#define NCHUNK 4
#define CHUNK_BYTES (32 * Hh * 4)     // 32 rows = 16KB

__global__ void __launch_bounds__(512) routing_kernel(const float* __restrict__ mask,
                                                      float* __restrict__ out,
                                                      int iter) {
    extern __shared__ float sm[];
    float* hat = sm;                       // [128][128] = 64KB
    float* sw  = sm + Ss * Hh;             // [128]
    float* cap = sw + Ss;                  // [128]
    float* red = cap + Hh;                 // [512]
    u64*   mb  = (u64*)(red + 512);        // [4] mbarriers

    const int bx  = blockIdx.x;            // b*K + k
    const int b   = bx >> 2;
    const int k   = bx & 3;
    const int tid = threadIdx.x;
    const float* hp = g_hat + (size_t)bx * (Ss * Hh);

    const uint32_t hat_a = (uint32_t)__cvta_generic_to_shared(hat);
    const uint32_t mb_a  = (uint32_t)__cvta_generic_to_shared(mb);

    if (tid == 0) {
        #pragma unroll
        for (int c = 0; c < NCHUNK; c++) mbar_init(mb_a + c * 8, 1);
    }
    __syncthreads();
    if (tid == 0) {
        #pragma unroll
        for (int c = 0; c < NCHUNK; c++) {
            mbar_expect_tx(mb_a + c * 8, CHUNK_BYTES);
            bulk_g2s(hat_a + c * CHUNK_BYTES, hp + c * (32 * Hh),
                     CHUNK_BYTES, mb_a + c * 8);
        }
    }

    // ---- sw[s] (independent of hat; overlaps the copies)
    if (tid < Ss) {
        float m = mask[b * Ss + tid];
        float v;
        if (iter == 0) {
            v = 1.0f / (float)Bb;                       // softmax over b of zeros
        } else {
            float e = __expf(g_cw[(size_t)bx * Ss + tid]);
            v = e / g_dacc[iter - 1][k * Ss + tid];
        }
        sw[tid] = (m == 0.0f) ? 0.0f : v;
    }
    __syncthreads();

    // ---- cap partial: quarter q handles rows [32q, 32q+32)
    {
        const int h = tid & 127, q = tid >> 7;
        mbar_wait(mb_a + q * 8, 0);
        const float* hq = hat + q * 32 * Hh + h;
        const float* sq = sw + q * 32;
        float acc = 0.0f;
        #pragma unroll
        for (int j = 0; j < 32; j++)
            acc += sq[j] * hq[j * Hh];
        red[tid] = acc;
    }
    __syncthreads();
    if (tid < Hh)
        cap[tid] = red[tid] + red[128 + tid] + red[256 + tid] + red[384 + tid];
    __syncthreads();

    // ---- squash (first 128 threads)
    {
        float v = (tid < Hh) ? cap[tid] * cap[tid] : 0.0f;
        #pragma unroll
        for (int off = 16; off; off >>= 1)
            v += __shfl_down_sync(0xffffffffu, v, off);
        if (tid < Hh && (tid & 31) == 0) red[tid >> 5] = v;
        __syncthreads();
        if (tid == 0) {
            float n = red[0] + red[1] + red[2] + red[3];
            red[8] = n / (1.0f + n) * rsqrtf(n + EPSQ);
        }
        __syncthreads();
        float f = red[8];
        if (tid < Hh) cap[tid] *= f;
    }
    __syncthreads();

    if (iter < 2) {
        // ---- delta[s] = hat[s][:] . cap ; update cw ; accumulate exp(cw)
        const int warp = tid >> 5, lane = tid & 31;
        #pragma unroll
        for (int s = warp; s < Ss; s += 16) {
            const float* q = hat + s * Hh;
            float d = 0.0f;
            #pragma unroll
            for (int i = 0; i < 4; i++)
                d += q[lane + 32 * i] * cap[lane + 32 * i];
            #pragma unroll
            for (int off = 16; off; off >>= 1)
                d += __shfl_down_sync(0xffffffffu, d, off);
            if (lane == 0) {
                size_t idx = (size_t)bx * Ss + s;
                float nc = (iter == 0) ? d : (g_cw[idx] + d);
                g_cw[idx] = nc;
                atomicAdd(&g_dacc[iter][k * Ss + s], __expf(nc));
            }
        }
    } else {
        if (tid < Hh) out[(size_t)bx * Hh + tid] = cap[tid];
    }
}

// ---------------- launch -----------------------------------------------------
#define GSMEM (GBK * (GBM + GBN) * (int)sizeof(float))                  // 64KB
#define RSMEM ((Ss * Hh + Ss + Hh + 512) * (int)sizeof(float) + 64)     // ~68.7KB

extern "C" void kernel_launch(void* const* d_in, const int* in_sizes, int n_in,
                              void* d_out, int out_size) {
    const float* item = (const float*)d_in[0];   // [B,S,H]
    const float* mask = (const float*)d_in[1];   // [B,S]
    const float* w    = (const float*)d_in[2];   // [1,S,K*H,H]
    float* out = (float*)d_out;                  // [B,K,H]

    cudaFuncSetAttribute(gemm_kernel,
                         cudaFuncAttributeMaxDynamicSharedMemorySize, GSMEM);
    cudaFuncSetAttribute(routing_kernel,
                         cudaFuncAttributeMaxDynamicSharedMemorySize, RSMEM);

    zero_dacc<<<1, 1024>>>();

    dim3 gg(KH / GBN, Bb / GBM, Ss);
    gemm_kernel<<<gg, 128, GSMEM>>>(item, w);

    routing_kernel<<<Bb * Kk, 512, RSMEM>>>(mask, out, 0);
    routing_kernel<<<Bb * Kk, 512, RSMEM>>>(mask, out, 1);
    routing_kernel<<<Bb * Kk, 512, RSMEM>>>(mask, out, 2);
}

// round 7
// speedup vs baseline: 1.7868x; 1.3460x over previous
#include <cuda_runtime.h>
#include <cstdint>

#define Bb 512
#define Ss 128
#define Kk 4
#define Hh 128
#define KH 512
#define EPSQ 1e-9f

typedef unsigned long long u64;

// ---------------- scratch (device globals; no allocation allowed) ----------
__device__ float g_hat[(size_t)Bb * Kk * Ss * Hh];   // 134 MB: hat[b][k][s][h]
__device__ float g_cw[(size_t)Bb * Kk * Ss];         // capsule_weight
__device__ float g_dacc[2][Kk * Ss];                 // softmax denom accumulators

// ---------------- mbarrier / bulk-copy helpers ------------------------------
__device__ __forceinline__ void mbar_init(uint32_t mbar, uint32_t cnt) {
    asm volatile("mbarrier.init.shared.b64 [%0], %1;" :: "r"(mbar), "r"(cnt) : "memory");
}
__device__ __forceinline__ void mbar_expect_tx(uint32_t mbar, uint32_t bytes) {
    asm volatile("mbarrier.arrive.expect_tx.shared.b64 _, [%0], %1;"
                 :: "r"(mbar), "r"(bytes) : "memory");
}
__device__ __forceinline__ void bulk_g2s(uint32_t dst, const void* src,
                                         uint32_t bytes, uint32_t mbar) {
    asm volatile(
        "cp.async.bulk.shared::cluster.global.mbarrier::complete_tx::bytes "
        "[%0], [%1], %2, [%3];"
        :: "r"(dst), "l"(src), "r"(bytes), "r"(mbar) : "memory");
}
__device__ __forceinline__ void mbar_wait(uint32_t mbar, uint32_t phase) {
    asm volatile(
        "{\n\t.reg .pred P;\n\t"
        "WL%=:\n\t"
        "mbarrier.try_wait.parity.shared.b64 P, [%0], %1;\n\t"
        "@!P bra WL%=;\n\t}"
        :: "r"(mbar), "r"(phase) : "memory");
}

// ---------------- tf32 mma helpers (generic PTX, works on compute_103) ------
__device__ __forceinline__ uint32_t tf32_bits(float x) {
    uint32_t u;
    asm("cvt.rna.tf32.f32 %0, %1;" : "=r"(u) : "f"(x));
    return u;
}
__device__ __forceinline__ void ldsm4(uint32_t* r, uint32_t addr) {
    asm volatile("ldmatrix.sync.aligned.m8n8.x4.shared.b16 {%0,%1,%2,%3}, [%4];"
                 : "=r"(r[0]), "=r"(r[1]), "=r"(r[2]), "=r"(r[3]) : "r"(addr));
}
__device__ __forceinline__ void mma8(float* d, const uint32_t* a,
                                     uint32_t b0, uint32_t b1) {
    asm volatile(
        "mma.sync.aligned.m16n8k8.row.col.f32.tf32.tf32.f32 "
        "{%0,%1,%2,%3}, {%4,%5,%6,%7}, {%8,%9}, {%0,%1,%2,%3};"
        : "+f"(d[0]), "+f"(d[1]), "+f"(d[2]), "+f"(d[3])
        : "r"(a[0]), "r"(a[1]), "r"(a[2]), "r"(a[3]), "r"(b0), "r"(b1));
}

// ---------------- tensor-core TF32 GEMM --------------------------------------
// hat[b,kcap,s,h] = sum_k item[b,s,k] * w[s, kcap*H+h, k]   (3xTF32)
// A = w rows (M = h/d, 128), B = item rows (N = b, 128), K = 128 in 4 chunks.
// smem chunk tiles (row-major, 32 k = 128B rows, swizzled): Ah, Al, Bh, Bl.
#define TCHUNK_B 16384     // one [128 x 32] f32 tile
#define GEMM_SMEM (128 * 132 * 4)   // 67584B (staging 64KB fits inside)

__global__ void __launch_bounds__(256) gemm_mma(const float* __restrict__ item,
                                                const float* __restrict__ w) {
    extern __shared__ float sm[];
    char* smc = (char*)sm;
    const uint32_t sb = (uint32_t)__cvta_generic_to_shared(sm);

    const int tid  = threadIdx.x;
    const int warp = tid >> 5, lane = tid & 31;
    const int kcap = blockIdx.x;
    const int d0   = kcap * 128;
    const int b0   = blockIdx.y * 128;
    const int s    = blockIdx.z;

    const int wm = warp & 1;           // m half (64)
    const int wn = warp >> 1;          // n quarter (32)
    const int m_base = wm * 64;
    const int n_base = wn * 32;

    const float* Ag = w    + ((size_t)s * KH + d0) * Hh;
    const float* Bg = item + ((size_t)b0 * Ss + s) * Hh;

    // ldmatrix per-lane row addresses (q = matrix quadrant)
    const int q = lane >> 3, rr = lane & 7;
    uint32_t rowA[4], rowB[2];
    {
        const int mA = m_base + (q & 1) * 8 + rr;
        #pragma unroll
        for (int mt = 0; mt < 4; mt++) {
            int m = mA + mt * 16;
            rowA[mt] = sb + (uint32_t)(m * 128) + ((((m & 7) ^ (q >> 1)) << 4));
        }
        const int nB = n_base + (q >> 1) * 8 + rr;
        #pragma unroll
        for (int nt = 0; nt < 2; nt++) {
            int n = nB + nt * 16;
            rowB[nt] = sb + 32768u + (uint32_t)(n * 128) + ((((n & 7) ^ (q & 1)) << 4));
        }
    }

    float acc[4][4][4];
    #pragma unroll
    for (int i = 0; i < 4; i++)
        #pragma unroll
        for (int j = 0; j < 4; j++)
            #pragma unroll
            for (int e = 0; e < 4; e++) acc[i][j][e] = 0.0f;

    const int f4 = tid & 7;      // kunit (16B within 128B row)
    const int r0 = tid >> 3;     // 0..31

    for (int c = 0; c < 4; c++) {
        __syncthreads();
        // ---- stage chunk c: LDG.128 -> tf32 hi/lo split -> swizzled STS.128
        #pragma unroll
        for (int p = 0; p < 4; p++) {
            const int row = r0 + p * 32;
            const uint32_t so = (uint32_t)(row * 128) + (((uint32_t)(f4 ^ (row & 7))) << 4);

            float4 va = *(const float4*)(Ag + (size_t)row * Hh + c * 32 + f4 * 4);
            uint4 hi, lo;
            hi.x = tf32_bits(va.x); lo.x = tf32_bits(va.x - __uint_as_float(hi.x));
            hi.y = tf32_bits(va.y); lo.y = tf32_bits(va.y - __uint_as_float(hi.y));
            hi.z = tf32_bits(va.z); lo.z = tf32_bits(va.z - __uint_as_float(hi.z));
            hi.w = tf32_bits(va.w); lo.w = tf32_bits(va.w - __uint_as_float(hi.w));
            *(uint4*)(smc + so)         = hi;          // Ah
            *(uint4*)(smc + so + 16384) = lo;          // Al

            float4 vb = *(const float4*)(Bg + (size_t)row * (Ss * Hh) + c * 32 + f4 * 4);
            hi.x = tf32_bits(vb.x); lo.x = tf32_bits(vb.x - __uint_as_float(hi.x));
            hi.y = tf32_bits(vb.y); lo.y = tf32_bits(vb.y - __uint_as_float(hi.y));
            hi.z = tf32_bits(vb.z); lo.z = tf32_bits(vb.z - __uint_as_float(hi.z));
            hi.w = tf32_bits(vb.w); lo.w = tf32_bits(vb.w - __uint_as_float(hi.w));
            *(uint4*)(smc + so + 32768) = hi;          // Bh
            *(uint4*)(smc + so + 49152) = lo;          // Bl
        }
        __syncthreads();

        // ---- compute: 4 k8 steps, 3-term tf32 compensation
        #pragma unroll
        for (int kt = 0; kt < 4; kt++) {
            const uint32_t kx = (uint32_t)(kt << 5);
            uint32_t ah[4][4], al[4][4], bh[2][4], bl[2][4];
            #pragma unroll
            for (int mt = 0; mt < 4; mt++) {
                ldsm4(ah[mt], rowA[mt] ^ kx);
                ldsm4(al[mt], (rowA[mt] ^ kx) + 16384u);
            }
            #pragma unroll
            for (int nt = 0; nt < 2; nt++) {
                ldsm4(bh[nt], rowB[nt] ^ kx);
                ldsm4(bl[nt], (rowB[nt] ^ kx) + 16384u);
            }
            #pragma unroll
            for (int mt = 0; mt < 4; mt++) {
                #pragma unroll
                for (int j = 0; j < 4; j++) {
                    const int nt = j >> 1, pp = (j & 1) * 2;
                    mma8(acc[mt][j], ah[mt], bl[nt][pp], bl[nt][pp + 1]);
                    mma8(acc[mt][j], al[mt], bh[nt][pp], bh[nt][pp + 1]);
                    mma8(acc[mt][j], ah[mt], bh[nt][pp], bh[nt][pp + 1]);
                }
            }
        }
    }
    __syncthreads();

    // ---- epilogue: transpose through smem [n][m] (pitch 132), coalesced STG
    #pragma unroll
    for (int mt = 0; mt < 4; mt++) {
        #pragma unroll
        for (int j = 0; j < 4; j++) {
            const int m = m_base + mt * 16 + (lane >> 2);
            const int n = n_base + j * 8 + 2 * (lane & 3);
            sm[n * 132 + m]           = acc[mt][j][0];
            sm[(n + 1) * 132 + m]     = acc[mt][j][1];
            sm[n * 132 + m + 8]       = acc[mt][j][2];
            sm[(n + 1) * 132 + m + 8] = acc[mt][j][3];
        }
    }
    __syncthreads();
    for (int i = tid; i < 4096; i += 256) {
        const int n = i >> 5, mu = i & 31;
        float4 v = *(const float4*)&sm[n * 132 + mu * 4];
        const int b = b0 + n;
        *(float4*)&g_hat[(((size_t)b * Kk + kcap) * Ss + s) * Hh + mu * 4] = v;
    }
}

// ---------------- zero the denom accumulators -------------------------------
__global__ void zero_dacc() {
    ((float*)g_dacc)[threadIdx.x] = 0.0f;   // 1024 floats
}

// ---------------- persistent routing: 128 CTAs x 16 tiles, double-buffered --
#define RT_TILES 16
#define RT_CTAS  128
#define TILE_BYTES 65536               // one [128 s][128 h] f32 tile

__global__ void __launch_bounds__(512) routing_kernel(const float* __restrict__ mask,
                                                      float* __restrict__ out,
                                                      int iter) {
    extern __shared__ float sm[];
    float* sw  = sm + 32768;           // [128]
    float* cap = sw + 128;             // [128]
    float* red = cap + 128;            // [512]
    const uint32_t sb   = (uint32_t)__cvta_generic_to_shared(sm);
    const uint32_t mb_a = sb + (32768 + 128 + 128 + 512) * 4;

    const int tid = threadIdx.x;
    const int t0  = blockIdx.x * RT_TILES;

    if (tid == 0) { mbar_init(mb_a, 1); mbar_init(mb_a + 8, 1); }
    __syncthreads();
    if (tid == 0) {
        mbar_expect_tx(mb_a, TILE_BYTES);
        bulk_g2s(sb, g_hat + (size_t)t0 * (Ss * Hh), TILE_BYTES, mb_a);
    }

    for (int t = 0; t < RT_TILES; t++) {
        const int bx = t0 + t;
        const int b  = bx >> 2;
        const int k  = bx & 3;
        float* hat = sm + (t & 1) * 16384;

        // prefetch next tile into the other buffer (free: compute(t-1) done)
        if (tid == 0 && t + 1 < RT_TILES) {
            const uint32_t nb = mb_a + ((t + 1) & 1) * 8;
            mbar_expect_tx(nb, TILE_BYTES);
            bulk_g2s(sb + ((t + 1) & 1) * TILE_BYTES,
                     g_hat + (size_t)(bx + 1) * (Ss * Hh), TILE_BYTES, nb);
        }

        // ---- sw[s] (independent of hat)
        if (tid < Ss) {
            float m = mask[b * Ss + tid];
            float v;
            if (iter == 0) {
                v = 1.0f / (float)Bb;                  // softmax over b of zeros
            } else {
                float e = __expf(g_cw[(size_t)bx * Ss + tid]);
                v = e / g_dacc[iter - 1][k * Ss + tid];
            }
            sw[tid] = (m == 0.0f) ? 0.0f : v;
        }
        __syncthreads();

        // ---- wait tile, cap partials: quarter q handles rows [32q, 32q+32)
        mbar_wait(mb_a + (t & 1) * 8, (t >> 1) & 1);
        {
            const int h = tid & 127, qq = tid >> 7;
            const float* hq = hat + qq * 32 * Hh + h;
            const float* sq = sw + qq * 32;
            float acc = 0.0f;
            #pragma unroll
            for (int j = 0; j < 32; j++)
                acc += sq[j] * hq[j * Hh];
            red[tid] = acc;
        }
        __syncthreads();
        if (tid < Hh)
            cap[tid] = red[tid] + red[128 + tid] + red[256 + tid] + red[384 + tid];
        __syncthreads();

        // ---- squash
        {
            float v = (tid < Hh) ? cap[tid] * cap[tid] : 0.0f;
            #pragma unroll
            for (int off = 16; off; off >>= 1)
                v += __shfl_down_sync(0xffffffffu, v, off);
            if (tid < Hh && (tid & 31) == 0) red[tid >> 5] = v;
            __syncthreads();
            if (tid == 0) {
                float n = red[0] + red[1] + red[2] + red[3];
                red[8] = n / (1.0f + n) * rsqrtf(n + EPSQ);
            }
            __syncthreads();
            float f = red[8];
            if (tid < Hh) cap[tid] *= f;
        }
        __syncthreads();

        if (iter < 2) {
            // ---- delta[s] = hat[s][:] . cap ; update cw ; accumulate exp(cw)
            const int warp = tid >> 5, lane = tid & 31;
            #pragma unroll
            for (int s = warp; s < Ss; s += 16) {
                const float* qp = hat + s * Hh;
                float d = 0.0f;
                #pragma unroll
                for (int i = 0; i < 4; i++)
                    d += qp[lane + 32 * i] * cap[lane + 32 * i];
                #pragma unroll
                for (int off = 16; off; off >>= 1)
                    d += __shfl_down_sync(0xffffffffu, d, off);
                if (lane == 0) {
                    size_t idx = (size_t)bx * Ss + s;
                    float nc = (iter == 0) ? d : (g_cw[idx] + d);
                    g_cw[idx] = nc;
                    atomicAdd(&g_dacc[iter][k * Ss + s], __expf(nc));
                }
            }
        } else {
            if (tid < Hh) out[(size_t)bx * Hh + tid] = cap[tid];
        }
        __syncthreads();   // protect buffers/sw before next tile's prefetch
    }
}

// ---------------- launch -----------------------------------------------------
#define RSMEM ((32768 + 128 + 128 + 512) * 4 + 32)   // ~134.3KB

extern "C" void kernel_launch(void* const* d_in, const int* in_sizes, int n_in,
                              void* d_out, int out_size) {
    const float* item = (const float*)d_in[0];   // [B,S,H]
    const float* mask = (const float*)d_in[1];   // [B,S]
    const float* w    = (const float*)d_in[2];   // [1,S,K*H,H]
    float* out = (float*)d_out;                  // [B,K,H]

    cudaFuncSetAttribute(gemm_mma,
                         cudaFuncAttributeMaxDynamicSharedMemorySize, GEMM_SMEM);
    cudaFuncSetAttribute(routing_kernel,
                         cudaFuncAttributeMaxDynamicSharedMemorySize, RSMEM);

    zero_dacc<<<1, 1024>>>();

    dim3 gg(Kk, Bb / 128, Ss);                   // (capsule, b-block, s)
    gemm_mma<<<gg, 256, GEMM_SMEM>>>(item, w);

    routing_kernel<<<RT_CTAS, 512, RSMEM>>>(mask, out, 0);
    routing_kernel<<<RT_CTAS, 512, RSMEM>>>(mask, out, 1);
    routing_kernel<<<RT_CTAS, 512, RSMEM>>>(mask, out, 2);
}

// round 10
// speedup vs baseline: 1.8763x; 1.0501x over previous
#include <cuda_runtime.h>
#include <cuda_fp16.h>
#include <cstdint>

#define Bb 512
#define Ss 128
#define Kk 4
#define Hh 128
#define KH 512
#define EPSQ 1e-9f

typedef unsigned long long u64;

// ---------------- scratch (device globals; no allocation allowed) ----------
__device__ float  g_hat  [(size_t)Bb * Kk * Ss * Hh];  // 134 MB fp32 hat
__device__ __half g_hat_h[(size_t)Bb * Kk * Ss * Hh];  // 67 MB fp16 copy (routing)
__device__ float  g_cw   [(size_t)Bb * Kk * Ss];       // capsule_weight
__device__ float  g_dacc [2][Kk * Ss];                 // softmax denominators

// ---------------- tf32 mma helpers (generic PTX, compute_103-safe) ----------
__device__ __forceinline__ uint32_t tf32_bits(float x) {
    uint32_t u;
    asm("cvt.rna.tf32.f32 %0, %1;" : "=r"(u) : "f"(x));
    return u;
}
__device__ __forceinline__ void ldsm4(uint32_t* r, uint32_t addr) {
    asm volatile("ldmatrix.sync.aligned.m8n8.x4.shared.b16 {%0,%1,%2,%3}, [%4];"
                 : "=r"(r[0]), "=r"(r[1]), "=r"(r[2]), "=r"(r[3]) : "r"(addr));
}
__device__ __forceinline__ void mma8(float* d, const uint32_t* a,
                                     uint32_t b0, uint32_t b1) {
    asm volatile(
        "mma.sync.aligned.m16n8k8.row.col.f32.tf32.tf32.f32 "
        "{%0,%1,%2,%3}, {%4,%5,%6,%7}, {%8,%9}, {%0,%1,%2,%3};"
        : "+f"(d[0]), "+f"(d[1]), "+f"(d[2]), "+f"(d[3])
        : "r"(a[0]), "r"(a[1]), "r"(a[2]), "r"(a[3]), "r"(b0), "r"(b1));
}

// ---------------- tensor-core TF32 GEMM --------------------------------------
// hat[b,kcap,s,h] = sum_k item[b,s,k] * w[s, kcap*H+h, k]   (3xTF32)
#define GEMM_SMEM (128 * 132 * 4)   // 67584B (64KB staging fits inside)

__global__ void __launch_bounds__(256) gemm_mma(const float* __restrict__ item,
                                                const float* __restrict__ w) {
    extern __shared__ float sm[];
    char* smc = (char*)sm;
    const uint32_t sb = (uint32_t)__cvta_generic_to_shared(sm);

    const int tid  = threadIdx.x;
    const int warp = tid >> 5, lane = tid & 31;
    const int kcap = blockIdx.x;
    const int d0   = kcap * 128;
    const int b0   = blockIdx.y * 128;
    const int s    = blockIdx.z;

    const int wm = warp & 1;           // m half (64)
    const int wn = warp >> 1;          // n quarter (32)
    const int m_base = wm * 64;
    const int n_base = wn * 32;

    const float* Ag = w    + ((size_t)s * KH + d0) * Hh;
    const float* Bg = item + ((size_t)b0 * Ss + s) * Hh;

    // ldmatrix per-lane row addresses (q = matrix quadrant)
    const int q = lane >> 3, rr = lane & 7;
    uint32_t rowA[4], rowB[2];
    {
        const int mA = m_base + (q & 1) * 8 + rr;
        #pragma unroll
        for (int mt = 0; mt < 4; mt++) {
            int m = mA + mt * 16;
            rowA[mt] = sb + (uint32_t)(m * 128) + ((((m & 7) ^ (q >> 1)) << 4));
        }
        const int nB = n_base + (q >> 1) * 8 + rr;
        #pragma unroll
        for (int nt = 0; nt < 2; nt++) {
            int n = nB + nt * 16;
            rowB[nt] = sb + 32768u + (uint32_t)(n * 128) + ((((n & 7) ^ (q & 1)) << 4));
        }
    }

    float acc[4][4][4];
    #pragma unroll
    for (int i = 0; i < 4; i++)
        #pragma unroll
        for (int j = 0; j < 4; j++)
            #pragma unroll
            for (int e = 0; e < 4; e++) acc[i][j][e] = 0.0f;

    const int f4 = tid & 7;      // kunit (16B within 128B row)
    const int r0 = tid >> 3;     // 0..31

    for (int c = 0; c < 4; c++) {
        __syncthreads();
        // ---- stage chunk c: LDG.128 -> tf32 hi/lo split -> swizzled STS.128
        #pragma unroll
        for (int p = 0; p < 4; p++) {
            const int row = r0 + p * 32;
            const uint32_t so = (uint32_t)(row * 128) + (((uint32_t)(f4 ^ (row & 7))) << 4);

            float4 va = *(const float4*)(Ag + (size_t)row * Hh + c * 32 + f4 * 4);
            uint4 hi, lo;
            hi.x = tf32_bits(va.x); lo.x = tf32_bits(va.x - __uint_as_float(hi.x));
            hi.y = tf32_bits(va.y); lo.y = tf32_bits(va.y - __uint_as_float(hi.y));
            hi.z = tf32_bits(va.z); lo.z = tf32_bits(va.z - __uint_as_float(hi.z));
            hi.w = tf32_bits(va.w); lo.w = tf32_bits(va.w - __uint_as_float(hi.w));
            *(uint4*)(smc + so)         = hi;          // Ah
            *(uint4*)(smc + so + 16384) = lo;          // Al

            float4 vb = *(const float4*)(Bg + (size_t)row * (Ss * Hh) + c * 32 + f4 * 4);
            hi.x = tf32_bits(vb.x); lo.x = tf32_bits(vb.x - __uint_as_float(hi.x));
            hi.y = tf32_bits(vb.y); lo.y = tf32_bits(vb.y - __uint_as_float(hi.y));
            hi.z = tf32_bits(vb.z); lo.z = tf32_bits(vb.z - __uint_as_float(hi.z));
            hi.w = tf32_bits(vb.w); lo.w = tf32_bits(vb.w - __uint_as_float(hi.w));
            *(uint4*)(smc + so + 32768) = hi;          // Bh
            *(uint4*)(smc + so + 49152) = lo;          // Bl
        }
        __syncthreads();

        // ---- compute: 4 k8 steps, 3-term tf32 compensation
        #pragma unroll
        for (int kt = 0; kt < 4; kt++) {
            const uint32_t kx = (uint32_t)(kt << 5);
            uint32_t ah[4][4], al[4][4], bh[2][4], bl[2][4];
            #pragma unroll
            for (int mt = 0; mt < 4; mt++) {
                ldsm4(ah[mt], rowA[mt] ^ kx);
                ldsm4(al[mt], (rowA[mt] ^ kx) + 16384u);
            }
            #pragma unroll
            for (int nt = 0; nt < 2; nt++) {
                ldsm4(bh[nt], rowB[nt] ^ kx);
                ldsm4(bl[nt], (rowB[nt] ^ kx) + 16384u);
            }
            #pragma unroll
            for (int mt = 0; mt < 4; mt++) {
                #pragma unroll
                for (int j = 0; j < 4; j++) {
                    const int nt = j >> 1, pp = (j & 1) * 2;
                    mma8(acc[mt][j], ah[mt], bl[nt][pp], bl[nt][pp + 1]);
                    mma8(acc[mt][j], al[mt], bh[nt][pp], bh[nt][pp + 1]);
                    mma8(acc[mt][j], ah[mt], bh[nt][pp], bh[nt][pp + 1]);
                }
            }
        }
    }
    __syncthreads();

    // ---- epilogue: transpose through smem [n][m] (pitch 132), coalesced STG
    #pragma unroll
    for (int mt = 0; mt < 4; mt++) {
        #pragma unroll
        for (int j = 0; j < 4; j++) {
            const int m = m_base + mt * 16 + (lane >> 2);
            const int n = n_base + j * 8 + 2 * (lane & 3);
            sm[n * 132 + m]           = acc[mt][j][0];
            sm[(n + 1) * 132 + m]     = acc[mt][j][1];
            sm[n * 132 + m + 8]       = acc[mt][j][2];
            sm[(n + 1) * 132 + m + 8] = acc[mt][j][3];
        }
    }
    __syncthreads();
    for (int i = tid; i < 4096; i += 256) {
        const int n = i >> 5, mu = i & 31;
        float4 v = *(const float4*)&sm[n * 132 + mu * 4];
        const int b = b0 + n;
        const size_t off = (((size_t)b * Kk + kcap) * Ss + s) * Hh + mu * 4;
        *(float4*)&g_hat[off] = v;
        union { __half2 h[2]; uint2 u; } cv;
        cv.h[0] = __floats2half2_rn(v.x, v.y);
        cv.h[1] = __floats2half2_rn(v.z, v.w);
        *(uint2*)&g_hat_h[off] = cv.u;
    }
}

// ---------------- zero the denom accumulators -------------------------------
__global__ void zero_dacc() {
    ((float*)g_dacc)[threadIdx.x] = 0.0f;   // 1024 floats
}

// ---------------- routing iters 0/1: fp16 hat, one (b,k) per CTA -----------
#define R01_SMEM (32768 + (128 + 128 + 256 + 16) * 4)

__global__ void __launch_bounds__(256) routing01(const float* __restrict__ mask,
                                                 int iter) {
    extern __shared__ char smraw[];
    __half* hat = (__half*)smraw;                   // [128][128] fp16 = 32KB
    float*  sw  = (float*)(smraw + 32768);          // [128]
    float*  cap = sw + 128;                         // [128]
    float*  red = cap + 128;                        // [256]

    const int bx  = blockIdx.x;   // b*K + k
    const int b   = bx >> 2;
    const int k   = bx & 3;
    const int tid = threadIdx.x;

    // ---- stage fp16 tile (32 KB, 8 x uint4 per thread, fully coalesced)
    {
        const uint4* src = (const uint4*)(g_hat_h + (size_t)bx * (Ss * Hh));
        uint4* dst = (uint4*)hat;
        #pragma unroll
        for (int i = 0; i < 8; i++)
            dst[tid + i * 256] = src[tid + i * 256];
    }

    // ---- sw[s]
    if (tid < Ss) {
        float m = mask[b * Ss + tid];
        float v;
        if (iter == 0) {
            v = 1.0f / (float)Bb;                       // softmax over b of zeros
        } else {
            float e = __expf(g_cw[(size_t)bx * Ss + tid]);
            v = e / g_dacc[0][k * Ss + tid];
        }
        sw[tid] = (m == 0.0f) ? 0.0f : v;
    }
    __syncthreads();

    // ---- cap[h] = sum_s sw[s]*hat[s][h]   (two s-halves across 256 threads)
    {
        const int h = tid & 127, half = tid >> 7;
        const __half* hq = hat + half * 64 * Hh + h;
        const float*  sq = sw + half * 64;
        float acc = 0.0f;
        #pragma unroll 16
        for (int j = 0; j < 64; j++)
            acc += sq[j] * __half2float(hq[j * Hh]);
        red[tid] = acc;
    }
    __syncthreads();
    if (tid < Hh) cap[tid] = red[tid] + red[tid + 128];
    __syncthreads();

    // ---- squash
    {
        float v = (tid < Hh) ? cap[tid] * cap[tid] : 0.0f;
        #pragma unroll
        for (int off = 16; off; off >>= 1)
            v += __shfl_down_sync(0xffffffffu, v, off);
        if (tid < Hh && (tid & 31) == 0) red[tid >> 5] = v;
        __syncthreads();
        if (tid == 0) {
            float n = red[0] + red[1] + red[2] + red[3];
            red[8] = n / (1.0f + n) * rsqrtf(n + EPSQ);
        }
        __syncthreads();
        float f = red[8];
        if (tid < Hh) cap[tid] *= f;
    }
    __syncthreads();

    // ---- delta[s] = hat[s][:] . cap ; update cw ; accumulate exp(cw)
    {
        const int warp = tid >> 5, lane = tid & 31;
        #pragma unroll
        for (int s = warp; s < Ss; s += 8) {
            const __half* qp = hat + s * Hh;
            float d = 0.0f;
            #pragma unroll
            for (int i = 0; i < 4; i++)
                d += __half2float(qp[lane + 32 * i]) * cap[lane + 32 * i];
            #pragma unroll
            for (int off = 16; off; off >>= 1)
                d += __shfl_down_sync(0xffffffffu, d, off);
            if (lane == 0) {
                size_t idx = (size_t)bx * Ss + s;
                float nc = (iter == 0) ? d : (g_cw[idx] + d);
                g_cw[idx] = nc;
                atomicAdd(&g_dacc[iter][k * Ss + s], __expf(nc));
            }
        }
    }
}

// ---------------- final iteration: fp32 stream, cap+squash+out only --------
__global__ void __launch_bounds__(256) routing_final(const float* __restrict__ mask,
                                                     float* __restrict__ out) {
    __shared__ float sw[Ss];
    __shared__ float cap[Hh];
    __shared__ float red[256];

    const int bx  = blockIdx.x;   // b*K + k
    const int b   = bx >> 2;
    const int k   = bx & 3;
    const int tid = threadIdx.x;

    if (tid < Ss) {
        float m = mask[b * Ss + tid];
        float e = __expf(g_cw[(size_t)bx * Ss + tid]);
        float v = e / g_dacc[1][k * Ss + tid];
        sw[tid] = (m == 0.0f) ? 0.0f : v;
    }
    __syncthreads();

    // cap partials straight from gmem (each element read exactly once)
    {
        const int h = tid & 127, half = tid >> 7;
        const float* hp = g_hat + (size_t)bx * (Ss * Hh) + half * 64 * Hh + h;
        const float* sq = sw + half * 64;
        float acc = 0.0f;
        #pragma unroll 8
        for (int j = 0; j < 64; j++)
            acc += sq[j] * hp[(size_t)j * Hh];
        red[tid] = acc;
    }
    __syncthreads();
    if (tid < Hh) cap[tid] = red[tid] + red[tid + 128];
    __syncthreads();

    // squash + output
    {
        float v = (tid < Hh) ? cap[tid] * cap[tid] : 0.0f;
        #pragma unroll
        for (int off = 16; off; off >>= 1)
            v += __shfl_down_sync(0xffffffffu, v, off);
        if (tid < Hh && (tid & 31) == 0) red[tid >> 5] = v;
        __syncthreads();
        if (tid == 0) {
            float n = red[0] + red[1] + red[2] + red[3];
            red[8] = n / (1.0f + n) * rsqrtf(n + EPSQ);
        }
        __syncthreads();
        if (tid < Hh) out[(size_t)bx * Hh + tid] = cap[tid] * red[8];
    }
}

// ---------------- launch -----------------------------------------------------
extern "C" void kernel_launch(void* const* d_in, const int* in_sizes, int n_in,
                              void* d_out, int out_size) {
    const float* item = (const float*)d_in[0];   // [B,S,H]
    const float* mask = (const float*)d_in[1];   // [B,S]
    const float* w    = (const float*)d_in[2];   // [1,S,K*H,H]
    float* out = (float*)d_out;                  // [B,K,H]

    cudaFuncSetAttribute(gemm_mma,
                         cudaFuncAttributeMaxDynamicSharedMemorySize, GEMM_SMEM);
    cudaFuncSetAttribute(routing01,
                         cudaFuncAttributeMaxDynamicSharedMemorySize, R01_SMEM);

    zero_dacc<<<1, 1024>>>();

    dim3 gg(Kk, Bb / 128, Ss);                   // (capsule, b-block, s)
    gemm_mma<<<gg, 256, GEMM_SMEM>>>(item, w);

    routing01<<<Bb * Kk, 256, R01_SMEM>>>(mask, 0);
    routing01<<<Bb * Kk, 256, R01_SMEM>>>(mask, 1);
    routing_final<<<Bb * Kk, 256>>>(mask, out);
}

// round 11
// speedup vs baseline: 2.9549x; 1.5748x over previous
#include <cuda_runtime.h>
#include <cuda_fp16.h>
#include <cstdint>

#define Bb 512
#define Ss 128
#define Kk 4
#define Hh 128
#define KH 512
#define EPSQ 1e-9f

typedef unsigned long long u64;

// ---------------- scratch (device globals; no allocation allowed) ----------
__device__ __half g_hat_h[(size_t)Bb * Kk * Ss * Hh];  // 67 MB fp16 hat
__device__ float  g_cw   [(size_t)Bb * Kk * Ss];       // capsule_weight
__device__ float  g_dacc [2][Kk * Ss];                 // softmax denominators

// ---------------- tf32 mma helpers (generic PTX, compute_103-safe) ----------
__device__ __forceinline__ uint32_t tf32_bits(float x) {
    uint32_t u;
    asm("cvt.rna.tf32.f32 %0, %1;" : "=r"(u) : "f"(x));
    return u;
}
__device__ __forceinline__ void ldsm4(uint32_t* r, uint32_t addr) {
    asm volatile("ldmatrix.sync.aligned.m8n8.x4.shared.b16 {%0,%1,%2,%3}, [%4];"
                 : "=r"(r[0]), "=r"(r[1]), "=r"(r[2]), "=r"(r[3]) : "r"(addr));
}
__device__ __forceinline__ void mma8(float* d, const uint32_t* a,
                                     uint32_t b0, uint32_t b1) {
    asm volatile(
        "mma.sync.aligned.m16n8k8.row.col.f32.tf32.tf32.f32 "
        "{%0,%1,%2,%3}, {%4,%5,%6,%7}, {%8,%9}, {%0,%1,%2,%3};"
        : "+f"(d[0]), "+f"(d[1]), "+f"(d[2]), "+f"(d[3])
        : "r"(a[0]), "r"(a[1]), "r"(a[2]), "r"(a[3]), "r"(b0), "r"(b1));
}

// ---------------- tensor-core TF32 GEMM --------------------------------------
// hat[b,kcap,s,h] = sum_k item[b,s,k] * w[s, kcap*H+h, k]   (3xTF32)
#define GEMM_SMEM (128 * 132 * 4)   // 67584B (64KB staging fits inside)

__global__ void __launch_bounds__(256) gemm_mma(const float* __restrict__ item,
                                                const float* __restrict__ w) {
    extern __shared__ float sm[];
    char* smc = (char*)sm;
    const uint32_t sb = (uint32_t)__cvta_generic_to_shared(sm);

    const int tid  = threadIdx.x;
    const int warp = tid >> 5, lane = tid & 31;
    const int kcap = blockIdx.x;
    const int d0   = kcap * 128;
    const int b0   = blockIdx.y * 128;
    const int s    = blockIdx.z;

    const int wm = warp & 1;           // m half (64)
    const int wn = warp >> 1;          // n quarter (32)
    const int m_base = wm * 64;
    const int n_base = wn * 32;

    const float* Ag = w    + ((size_t)s * KH + d0) * Hh;
    const float* Bg = item + ((size_t)b0 * Ss + s) * Hh;

    // ldmatrix per-lane row addresses (q = matrix quadrant)
    const int q = lane >> 3, rr = lane & 7;
    uint32_t rowA[4], rowB[2];
    {
        const int mA = m_base + (q & 1) * 8 + rr;
        #pragma unroll
        for (int mt = 0; mt < 4; mt++) {
            int m = mA + mt * 16;
            rowA[mt] = sb + (uint32_t)(m * 128) + ((((m & 7) ^ (q >> 1)) << 4));
        }
        const int nB = n_base + (q >> 1) * 8 + rr;
        #pragma unroll
        for (int nt = 0; nt < 2; nt++) {
            int n = nB + nt * 16;
            rowB[nt] = sb + 32768u + (uint32_t)(n * 128) + ((((n & 7) ^ (q & 1)) << 4));
        }
    }

    float acc[4][4][4];
    #pragma unroll
    for (int i = 0; i < 4; i++)
        #pragma unroll
        for (int j = 0; j < 4; j++)
            #pragma unroll
            for (int e = 0; e < 4; e++) acc[i][j][e] = 0.0f;

    const int f4 = tid & 7;      // kunit (16B within 128B row)
    const int r0 = tid >> 3;     // 0..31

    for (int c = 0; c < 4; c++) {
        __syncthreads();
        // ---- stage chunk c: LDG.128 -> tf32 hi/lo split -> swizzled STS.128
        #pragma unroll
        for (int p = 0; p < 4; p++) {
            const int row = r0 + p * 32;
            const uint32_t so = (uint32_t)(row * 128) + (((uint32_t)(f4 ^ (row & 7))) << 4);

            float4 va = *(const float4*)(Ag + (size_t)row * Hh + c * 32 + f4 * 4);
            uint4 hi, lo;
            hi.x = tf32_bits(va.x); lo.x = tf32_bits(va.x - __uint_as_float(hi.x));
            hi.y = tf32_bits(va.y); lo.y = tf32_bits(va.y - __uint_as_float(hi.y));
            hi.z = tf32_bits(va.z); lo.z = tf32_bits(va.z - __uint_as_float(hi.z));
            hi.w = tf32_bits(va.w); lo.w = tf32_bits(va.w - __uint_as_float(hi.w));
            *(uint4*)(smc + so)         = hi;          // Ah
            *(uint4*)(smc + so + 16384) = lo;          // Al

            float4 vb = *(const float4*)(Bg + (size_t)row * (Ss * Hh) + c * 32 + f4 * 4);
            hi.x = tf32_bits(vb.x); lo.x = tf32_bits(vb.x - __uint_as_float(hi.x));
            hi.y = tf32_bits(vb.y); lo.y = tf32_bits(vb.y - __uint_as_float(hi.y));
            hi.z = tf32_bits(vb.z); lo.z = tf32_bits(vb.z - __uint_as_float(hi.z));
            hi.w = tf32_bits(vb.w); lo.w = tf32_bits(vb.w - __uint_as_float(hi.w));
            *(uint4*)(smc + so + 32768) = hi;          // Bh
            *(uint4*)(smc + so + 49152) = lo;          // Bl
        }
        __syncthreads();

        // ---- compute: 4 k8 steps, 3-term tf32 compensation
        #pragma unroll
        for (int kt = 0; kt < 4; kt++) {
            const uint32_t kx = (uint32_t)(kt << 5);
            uint32_t ah[4][4], al[4][4], bh[2][4], bl[2][4];
            #pragma unroll
            for (int mt = 0; mt < 4; mt++) {
                ldsm4(ah[mt], rowA[mt] ^ kx);
                ldsm4(al[mt], (rowA[mt] ^ kx) + 16384u);
            }
            #pragma unroll
            for (int nt = 0; nt < 2; nt++) {
                ldsm4(bh[nt], rowB[nt] ^ kx);
                ldsm4(bl[nt], (rowB[nt] ^ kx) + 16384u);
            }
            #pragma unroll
            for (int mt = 0; mt < 4; mt++) {
                #pragma unroll
                for (int j = 0; j < 4; j++) {
                    const int nt = j >> 1, pp = (j & 1) * 2;
                    mma8(acc[mt][j], ah[mt], bl[nt][pp], bl[nt][pp + 1]);
                    mma8(acc[mt][j], al[mt], bh[nt][pp], bh[nt][pp + 1]);
                    mma8(acc[mt][j], ah[mt], bh[nt][pp], bh[nt][pp + 1]);
                }
            }
        }
    }
    __syncthreads();

    // ---- epilogue: transpose through smem [n][m] (pitch 132), coalesced STG
    #pragma unroll
    for (int mt = 0; mt < 4; mt++) {
        #pragma unroll
        for (int j = 0; j < 4; j++) {
            const int m = m_base + mt * 16 + (lane >> 2);
            const int n = n_base + j * 8 + 2 * (lane & 3);
            sm[n * 132 + m]           = acc[mt][j][0];
            sm[(n + 1) * 132 + m]     = acc[mt][j][1];
            sm[n * 132 + m + 8]       = acc[mt][j][2];
            sm[(n + 1) * 132 + m + 8] = acc[mt][j][3];
        }
    }
    __syncthreads();
    for (int i = tid; i < 4096; i += 256) {
        const int n = i >> 5, mu = i & 31;
        float4 v = *(const float4*)&sm[n * 132 + mu * 4];
        const int b = b0 + n;
        const size_t off = (((size_t)b * Kk + kcap) * Ss + s) * Hh + mu * 4;
        union { __half2 h[2]; uint2 u; } cv;
        cv.h[0] = __floats2half2_rn(v.x, v.y);
        cv.h[1] = __floats2half2_rn(v.z, v.w);
        *(uint2*)&g_hat_h[off] = cv.u;
    }
}

// ---------------- zero the denom accumulators -------------------------------
__global__ void zero_dacc() {
    ((float*)g_dacc)[threadIdx.x] = 0.0f;   // 1024 floats
}

// ---------------- routing iters 0/1: fp16 hat, half2-vectorized -------------
#define HP2 68                              // padded half2 per s-row
#define R01_SMEM ((Ss * HP2) * 4 + (128 + 128 + 512) * 4)

__global__ void __launch_bounds__(256) routing01(const float* __restrict__ mask,
                                                 int iter) {
    extern __shared__ char smraw[];
    __half2* hat2 = (__half2*)smraw;                     // [128][HP2] = 34816B
    float*   sw   = (float*)(smraw + Ss * HP2 * 4);      // [128]
    float*   cap  = sw + 128;                            // [128]
    float*   red  = cap + 128;                           // [512]

    const int bx  = blockIdx.x;   // b*K + k
    const int b   = bx >> 2;
    const int k   = bx & 3;
    const int tid = threadIdx.x;

    // ---- stage fp16 tile into padded smem (uint4 = 4 half2 per op)
    {
        const uint4* src = (const uint4*)(g_hat_h + (size_t)bx * (Ss * Hh));
        #pragma unroll
        for (int i = 0; i < 8; i++) {
            int idx = tid + i * 256;           // 2048 uint4 total
            int s   = idx >> 4;
            int c4  = idx & 15;                // uint4 index within row
            *(uint4*)&hat2[s * HP2 + c4 * 4] = src[idx];
        }
    }

    // ---- sw[s]
    if (tid < Ss) {
        float m = mask[b * Ss + tid];
        float v;
        if (iter == 0) {
            v = 1.0f / (float)Bb;                       // softmax over b of zeros
        } else {
            float e = __expf(g_cw[(size_t)bx * Ss + tid]);
            v = e / g_dacc[0][k * Ss + tid];
        }
        sw[tid] = (m == 0.0f) ? 0.0f : v;
    }
    __syncthreads();

    // ---- cap: thread = (s-quarter, h2 pair); 32 half2 loads each
    {
        const int h2 = tid & 63, sq = tid >> 6;
        const __half2* hp = hat2 + sq * 32 * HP2 + h2;
        const float* sq_w = sw + sq * 32;
        float2 acc = make_float2(0.0f, 0.0f);
        #pragma unroll 8
        for (int j = 0; j < 32; j++) {
            float2 f = __half22float2(hp[j * HP2]);
            float  wv = sq_w[j];
            acc.x += wv * f.x;
            acc.y += wv * f.y;
        }
        *(float2*)&red[sq * 128 + 2 * h2] = acc;
    }
    __syncthreads();
    if (tid < Hh)
        cap[tid] = red[tid] + red[128 + tid] + red[256 + tid] + red[384 + tid];
    __syncthreads();

    // ---- squash
    {
        float v = (tid < Hh) ? cap[tid] * cap[tid] : 0.0f;
        #pragma unroll
        for (int off = 16; off; off >>= 1)
            v += __shfl_down_sync(0xffffffffu, v, off);
        if (tid < Hh && (tid & 31) == 0) red[tid >> 5] = v;
        __syncthreads();
        if (tid == 0) {
            float n = red[0] + red[1] + red[2] + red[3];
            red[8] = n / (1.0f + n) * rsqrtf(n + EPSQ);
        }
        __syncthreads();
        float f = red[8];
        if (tid < Hh) cap[tid] *= f;
    }
    __syncthreads();

    // ---- delta: 4 rows/warp/step via 8-lane groups; 3 xor-shfls to reduce
    {
        const int warp = tid >> 5, lane = tid & 31;
        const int g = lane >> 3, il = lane & 7;
        #pragma unroll
        for (int t = 0; t < 4; t++) {
            const int s = t * 32 + warp * 4 + g;
            const __half2* hp = hat2 + s * HP2;
            float d = 0.0f;
            #pragma unroll
            for (int j = 0; j < 8; j++) {
                const int c = il + 8 * j;
                float2 f = __half22float2(hp[c]);
                float2 cv = *(const float2*)&cap[2 * c];
                d += f.x * cv.x + f.y * cv.y;
            }
            d += __shfl_xor_sync(0xffffffffu, d, 4);
            d += __shfl_xor_sync(0xffffffffu, d, 2);
            d += __shfl_xor_sync(0xffffffffu, d, 1);
            if (il == 0) {
                size_t idx = (size_t)bx * Ss + s;
                float nc = (iter == 0) ? d : (g_cw[idx] + d);
                g_cw[idx] = nc;
                atomicAdd(&g_dacc[iter][k * Ss + s], __expf(nc));
            }
        }
    }
}

// ---------------- final iteration: fp16 stream, cap+squash+out only --------
__global__ void __launch_bounds__(256) routing_final(const float* __restrict__ mask,
                                                     float* __restrict__ out) {
    __shared__ float sw[Ss];
    __shared__ float cap[Hh];
    __shared__ float red[512];

    const int bx  = blockIdx.x;   // b*K + k
    const int b   = bx >> 2;
    const int k   = bx & 3;
    const int tid = threadIdx.x;

    if (tid < Ss) {
        float m = mask[b * Ss + tid];
        float e = __expf(g_cw[(size_t)bx * Ss + tid]);
        float v = e / g_dacc[1][k * Ss + tid];
        sw[tid] = (m == 0.0f) ? 0.0f : v;
    }
    __syncthreads();

    // cap partials straight from gmem (half2 columns, fully coalesced)
    {
        const int h2 = tid & 63, sq = tid >> 6;
        const __half2* hp = (const __half2*)g_hat_h
                          + (size_t)bx * (Ss * Hh / 2) + sq * 32 * 64 + h2;
        const float* sq_w = sw + sq * 32;
        float2 acc = make_float2(0.0f, 0.0f);
        #pragma unroll 8
        for (int j = 0; j < 32; j++) {
            float2 f = __half22float2(hp[j * 64]);
            float  wv = sq_w[j];
            acc.x += wv * f.x;
            acc.y += wv * f.y;
        }
        *(float2*)&red[sq * 128 + 2 * h2] = acc;
    }
    __syncthreads();
    if (tid < Hh)
        cap[tid] = red[tid] + red[128 + tid] + red[256 + tid] + red[384 + tid];
    __syncthreads();

    // squash + output
    {
        float v = (tid < Hh) ? cap[tid] * cap[tid] : 0.0f;
        #pragma unroll
        for (int off = 16; off; off >>= 1)
            v += __shfl_down_sync(0xffffffffu, v, off);
        if (tid < Hh && (tid & 31) == 0) red[tid >> 5] = v;
        __syncthreads();
        if (tid == 0) {
            float n = red[0] + red[1] + red[2] + red[3];
            red[8] = n / (1.0f + n) * rsqrtf(n + EPSQ);
        }
        __syncthreads();
        if (tid < Hh) out[(size_t)bx * Hh + tid] = cap[tid] * red[8];
    }
}

// ---------------- launch -----------------------------------------------------
extern "C" void kernel_launch(void* const* d_in, const int* in_sizes, int n_in,
                              void* d_out, int out_size) {
    const float* item = (const float*)d_in[0];   // [B,S,H]
    const float* mask = (const float*)d_in[1];   // [B,S]
    const float* w    = (const float*)d_in[2];   // [1,S,K*H,H]
    float* out = (float*)d_out;                  // [B,K,H]

    cudaFuncSetAttribute(gemm_mma,
                         cudaFuncAttributeMaxDynamicSharedMemorySize, GEMM_SMEM);
    cudaFuncSetAttribute(routing01,
                         cudaFuncAttributeMaxDynamicSharedMemorySize, R01_SMEM);

    zero_dacc<<<1, 1024>>>();

    dim3 gg(Kk, Bb / 128, Ss);                   // (capsule, b-block, s)
    gemm_mma<<<gg, 256, GEMM_SMEM>>>(item, w);

    routing01<<<Bb * Kk, 256, R01_SMEM>>>(mask, 0);
    routing01<<<Bb * Kk, 256, R01_SMEM>>>(mask, 1);
    routing_final<<<Bb * Kk, 256>>>(mask, out);
}

// round 12
// speedup vs baseline: 3.4109x; 1.1544x over previous
#include <cuda_runtime.h>
#include <cuda_fp16.h>
#include <cstdint>

#define Bb 512
#define Ss 128
#define Kk 4
#define Hh 128
#define KH 512
#define EPSQ 1e-9f

typedef unsigned long long u64;

// ---------------- scratch (device globals; no allocation allowed) ----------
__device__ __half g_hat_h[(size_t)Bb * Kk * Ss * Hh];  // 67 MB fp16 hat
__device__ float  g_cw   [(size_t)Bb * Kk * Ss];       // capsule_weight
__device__ float  g_dacc [2][Kk * Ss];                 // softmax denominators

// ---------------- mma helpers (generic PTX, compute_103-safe) ---------------
__device__ __forceinline__ void ldsm4(uint32_t* r, uint32_t addr) {
    asm volatile("ldmatrix.sync.aligned.m8n8.x4.shared.b16 {%0,%1,%2,%3}, [%4];"
                 : "=r"(r[0]), "=r"(r[1]), "=r"(r[2]), "=r"(r[3]) : "r"(addr));
}
__device__ __forceinline__ void mma16816(float* d, const uint32_t* a,
                                         uint32_t b0, uint32_t b1) {
    asm volatile(
        "mma.sync.aligned.m16n8k16.row.col.f32.f16.f16.f32 "
        "{%0,%1,%2,%3}, {%4,%5,%6,%7}, {%8,%9}, {%0,%1,%2,%3};"
        : "+f"(d[0]), "+f"(d[1]), "+f"(d[2]), "+f"(d[3])
        : "r"(a[0]), "r"(a[1]), "r"(a[2]), "r"(a[3]), "r"(b0), "r"(b1));
}

// split 8 fp32 into fp16 hi (uint4) + fp16 lo residual (uint4)
__device__ __forceinline__ void pack_split(float4 v0, float4 v1,
                                           uint4& hi, uint4& lo) {
    __half2 h; float2 f;
    h = __floats2half2_rn(v0.x, v0.y); hi.x = *(uint32_t*)&h;
    f = __half22float2(h);
    h = __floats2half2_rn(v0.x - f.x, v0.y - f.y); lo.x = *(uint32_t*)&h;
    h = __floats2half2_rn(v0.z, v0.w); hi.y = *(uint32_t*)&h;
    f = __half22float2(h);
    h = __floats2half2_rn(v0.z - f.x, v0.w - f.y); lo.y = *(uint32_t*)&h;
    h = __floats2half2_rn(v1.x, v1.y); hi.z = *(uint32_t*)&h;
    f = __half22float2(h);
    h = __floats2half2_rn(v1.x - f.x, v1.y - f.y); lo.z = *(uint32_t*)&h;
    h = __floats2half2_rn(v1.z, v1.w); hi.w = *(uint32_t*)&h;
    f = __half22float2(h);
    h = __floats2half2_rn(v1.z - f.x, v1.w - f.y); lo.w = *(uint32_t*)&h;
}

// ---------------- fp16 3-term tensor-core GEMM -------------------------------
// hat[b,kcap,s,h] = sum_k item[b,s,k] * w[s, kcap*H+h, k]
// A = w rows (M=128), B = item rows (N=128), K=128 in 2 chunks of 64.
// smem per chunk: Ah, Al, Bh, Bl each [128 rows][64 fp16] = 16KB -> 64KB.
#define GEMM_SMEM 65536

__global__ void __launch_bounds__(256, 2) gemm_mma(const float* __restrict__ item,
                                                   const float* __restrict__ w) {
    extern __shared__ char smc[];
    const uint32_t sb = (uint32_t)__cvta_generic_to_shared(smc);

    const int tid  = threadIdx.x;
    const int warp = tid >> 5, lane = tid & 31;
    const int kcap = blockIdx.x;
    const int d0   = kcap * 128;
    const int b0   = blockIdx.y * 128;
    const int s    = blockIdx.z;

    const int wm = warp & 1;             // m half (64 rows = 4 m16 tiles)
    const int wn = warp >> 1;            // n quarter (32 = 4 n8 tiles)
    const int m_base = wm * 64;
    const int n_base = wn * 32;

    const float* Ag = w    + ((size_t)s * KH + d0) * Hh;
    const float* Bg = item + ((size_t)b0 * Ss + s) * Hh;

    // ldmatrix lane geometry
    const int q = lane >> 3, rr = lane & 7;
    // A quadrants: [m0-7,k0-7],[m8-15,k0-7],[m0-7,k8-15],[m8-15,k8-15]
    const int qa = q >> 1;                       // k-unit low bit
    uint32_t baseA[4]; int m7A[4];
    #pragma unroll
    for (int mt = 0; mt < 4; mt++) {
        const int m = m_base + mt * 16 + ((q & 1) << 3) + rr;
        baseA[mt] = sb + (uint32_t)(m * 128);
        m7A[mt]   = m & 7;
    }
    // B quadrants: [n0-7,k0-7],[n0-7,k8-15],[n8-15,k0-7],[n8-15,k8-15]
    const int qb = q & 1;                        // k-unit low bit
    uint32_t baseB[2]; int n7B[2];
    #pragma unroll
    for (int nt2 = 0; nt2 < 2; nt2++) {
        const int n = n_base + nt2 * 16 + ((q >> 1) << 3) + rr;
        baseB[nt2] = sb + 32768u + (uint32_t)(n * 128);
        n7B[nt2]   = n & 7;
    }

    float acc[4][4][4];
    #pragma unroll
    for (int i = 0; i < 4; i++)
        #pragma unroll
        for (int j = 0; j < 4; j++)
            #pragma unroll
            for (int e = 0; e < 4; e++) acc[i][j][e] = 0.0f;

    const int u  = tid & 7;      // 16B unit within 128B chunk-row
    const int r0 = tid >> 3;     // 0..31

    #pragma unroll
    for (int c = 0; c < 2; c++) {
        __syncthreads();
        // ---- stage chunk c: LDG -> fp16 hi/lo split -> swizzled STS.128
        #pragma unroll
        for (int p = 0; p < 4; p++) {
            const int row = r0 + p * 32;
            const uint32_t so = (uint32_t)(row * 128) + ((uint32_t)(u ^ (row & 7)) << 4);

            const float* ap = Ag + (size_t)row * Hh + c * 64 + u * 8;
            float4 v0 = *(const float4*)ap, v1 = *(const float4*)(ap + 4);
            uint4 hi, lo;
            pack_split(v0, v1, hi, lo);
            *(uint4*)(smc + so)         = hi;    // Ah
            *(uint4*)(smc + so + 16384) = lo;    // Al

            const float* bp = Bg + (size_t)row * (Ss * Hh) + c * 64 + u * 8;
            v0 = *(const float4*)bp; v1 = *(const float4*)(bp + 4);
            pack_split(v0, v1, hi, lo);
            *(uint4*)(smc + so + 32768) = hi;    // Bh
            *(uint4*)(smc + so + 49152) = lo;    // Bl
        }
        __syncthreads();

        // ---- compute: 4 k16 steps, 3-term fp16 compensation
        #pragma unroll
        for (int kt = 0; kt < 4; kt++) {
            uint32_t bh[8], bl[8];
            #pragma unroll
            for (int nt2 = 0; nt2 < 2; nt2++) {
                const uint32_t ub = (uint32_t)((2 * kt + qb) ^ n7B[nt2]) << 4;
                ldsm4(&bh[nt2 * 4], baseB[nt2] + ub);
                ldsm4(&bl[nt2 * 4], baseB[nt2] + 16384u + ub);
            }
            #pragma unroll
            for (int mt = 0; mt < 4; mt++) {
                uint32_t ah[4], al[4];
                const uint32_t ua = (uint32_t)((2 * kt + qa) ^ m7A[mt]) << 4;
                ldsm4(ah, baseA[mt] + ua);
                ldsm4(al, baseA[mt] + 16384u + ua);
                #pragma unroll
                for (int nt = 0; nt < 4; nt++) {
                    mma16816(acc[mt][nt], ah, bl[nt * 2], bl[nt * 2 + 1]);
                    mma16816(acc[mt][nt], al, bh[nt * 2], bh[nt * 2 + 1]);
                    mma16816(acc[mt][nt], ah, bh[nt * 2], bh[nt * 2 + 1]);
                }
            }
        }
    }
    __syncthreads();

    // ---- epilogue: transpose to [n][m] fp16 (pitch 136), coalesced STG
    __half* smh = (__half*)smc;
    #pragma unroll
    for (int mt = 0; mt < 4; mt++) {
        #pragma unroll
        for (int nt = 0; nt < 4; nt++) {
            const int m = m_base + mt * 16 + (lane >> 2);
            const int n = n_base + nt * 8 + 2 * (lane & 3);
            smh[n * 136 + m]           = __float2half(acc[mt][nt][0]);
            smh[(n + 1) * 136 + m]     = __float2half(acc[mt][nt][1]);
            smh[n * 136 + m + 8]       = __float2half(acc[mt][nt][2]);
            smh[(n + 1) * 136 + m + 8] = __float2half(acc[mt][nt][3]);
        }
    }
    __syncthreads();
    #pragma unroll
    for (int i = tid; i < 2048; i += 256) {
        const int n = i >> 4, uo = i & 15;
        uint4 v = *(const uint4*)&smh[n * 136 + uo * 8];
        const int b = b0 + n;
        *(uint4*)&g_hat_h[(((size_t)b * Kk + kcap) * Ss + s) * Hh + uo * 8] = v;
    }
}

// ---------------- zero the denom accumulators -------------------------------
__global__ void zero_dacc() {
    ((float*)g_dacc)[threadIdx.x] = 0.0f;   // 1024 floats
}

// ---------------- routing iters 0/1: fp16 hat, half2-vectorized -------------
#define HP2 68                              // padded half2 per s-row
#define R01_SMEM ((Ss * HP2) * 4 + (128 + 128 + 512) * 4)

__global__ void __launch_bounds__(256) routing01(const float* __restrict__ mask,
                                                 int iter) {
    extern __shared__ char smraw[];
    __half2* hat2 = (__half2*)smraw;                     // [128][HP2] = 34816B
    float*   sw   = (float*)(smraw + Ss * HP2 * 4);      // [128]
    float*   cap  = sw + 128;                            // [128]
    float*   red  = cap + 128;                           // [512]

    const int bx  = blockIdx.x;   // b*K + k
    const int b   = bx >> 2;
    const int k   = bx & 3;
    const int tid = threadIdx.x;

    // ---- stage fp16 tile into padded smem (uint4 = 4 half2 per op)
    {
        const uint4* src = (const uint4*)(g_hat_h + (size_t)bx * (Ss * Hh));
        #pragma unroll
        for (int i = 0; i < 8; i++) {
            int idx = tid + i * 256;           // 2048 uint4 total
            int s   = idx >> 4;
            int c4  = idx & 15;                // uint4 index within row
            *(uint4*)&hat2[s * HP2 + c4 * 4] = src[idx];
        }
    }

    // ---- sw[s]
    if (tid < Ss) {
        float m = mask[b * Ss + tid];
        float v;
        if (iter == 0) {
            v = 1.0f / (float)Bb;                       // softmax over b of zeros
        } else {
            float e = __expf(g_cw[(size_t)bx * Ss + tid]);
            v = e / g_dacc[0][k * Ss + tid];
        }
        sw[tid] = (m == 0.0f) ? 0.0f : v;
    }
    __syncthreads();

    // ---- cap: thread = (s-quarter, h2 pair); 32 half2 loads each
    {
        const int h2 = tid & 63, sq = tid >> 6;
        const __half2* hp = hat2 + sq * 32 * HP2 + h2;
        const float* sq_w = sw + sq * 32;
        float2 acc = make_float2(0.0f, 0.0f);
        #pragma unroll 8
        for (int j = 0; j < 32; j++) {
            float2 f = __half22float2(hp[j * HP2]);
            float  wv = sq_w[j];
            acc.x += wv * f.x;
            acc.y += wv * f.y;
        }
        *(float2*)&red[sq * 128 + 2 * h2] = acc;
    }
    __syncthreads();
    if (tid < Hh)
        cap[tid] = red[tid] + red[128 + tid] + red[256 + tid] + red[384 + tid];
    __syncthreads();

    // ---- squash
    {
        float v = (tid < Hh) ? cap[tid] * cap[tid] : 0.0f;
        #pragma unroll
        for (int off = 16; off; off >>= 1)
            v += __shfl_down_sync(0xffffffffu, v, off);
        if (tid < Hh && (tid & 31) == 0) red[tid >> 5] = v;
        __syncthreads();
        if (tid == 0) {
            float n = red[0] + red[1] + red[2] + red[3];
            red[8] = n / (1.0f + n) * rsqrtf(n + EPSQ);
        }
        __syncthreads();
        float f = red[8];
        if (tid < Hh) cap[tid] *= f;
    }
    __syncthreads();

    // ---- delta: 4 rows/warp/step via 8-lane groups; 3 xor-shfls to reduce
    {
        const int warp = tid >> 5, lane = tid & 31;
        const int g = lane >> 3, il = lane & 7;
        #pragma unroll
        for (int t = 0; t < 4; t++) {
            const int s = t * 32 + warp * 4 + g;
            const __half2* hp = hat2 + s * HP2;
            float d = 0.0f;
            #pragma unroll
            for (int j = 0; j < 8; j++) {
                const int c = il + 8 * j;
                float2 f = __half22float2(hp[c]);
                float2 cv = *(const float2*)&cap[2 * c];
                d += f.x * cv.x + f.y * cv.y;
            }
            d += __shfl_xor_sync(0xffffffffu, d, 4);
            d += __shfl_xor_sync(0xffffffffu, d, 2);
            d += __shfl_xor_sync(0xffffffffu, d, 1);
            if (il == 0) {
                size_t idx = (size_t)bx * Ss + s;
                float nc = (iter == 0) ? d : (g_cw[idx] + d);
                g_cw[idx] = nc;
                atomicAdd(&g_dacc[iter][k * Ss + s], __expf(nc));
            }
        }
    }
}

// ---------------- final iteration: fp16 stream, cap+squash+out only --------
__global__ void __launch_bounds__(256) routing_final(const float* __restrict__ mask,
                                                     float* __restrict__ out) {
    __shared__ float sw[Ss];
    __shared__ float cap[Hh];
    __shared__ float red[512];

    const int bx  = blockIdx.x;   // b*K + k
    const int b   = bx >> 2;
    const int k   = bx & 3;
    const int tid = threadIdx.x;

    if (tid < Ss) {
        float m = mask[b * Ss + tid];
        float e = __expf(g_cw[(size_t)bx * Ss + tid]);
        float v = e / g_dacc[1][k * Ss + tid];
        sw[tid] = (m == 0.0f) ? 0.0f : v;
    }
    __syncthreads();

    // cap partials straight from gmem (half2 columns, fully coalesced)
    {
        const int h2 = tid & 63, sq = tid >> 6;
        const __half2* hp = (const __half2*)g_hat_h
                          + (size_t)bx * (Ss * Hh / 2) + sq * 32 * 64 + h2;
        const float* sq_w = sw + sq * 32;
        float2 acc = make_float2(0.0f, 0.0f);
        #pragma unroll 8
        for (int j = 0; j < 32; j++) {
            float2 f = __half22float2(hp[j * 64]);
            float  wv = sq_w[j];
            acc.x += wv * f.x;
            acc.y += wv * f.y;
        }
        *(float2*)&red[sq * 128 + 2 * h2] = acc;
    }
    __syncthreads();
    if (tid < Hh)
        cap[tid] = red[tid] + red[128 + tid] + red[256 + tid] + red[384 + tid];
    __syncthreads();

    // squash + output
    {
        float v = (tid < Hh) ? cap[tid] * cap[tid] : 0.0f;
        #pragma unroll
        for (int off = 16; off; off >>= 1)
            v += __shfl_down_sync(0xffffffffu, v, off);
        if (tid < Hh && (tid & 31) == 0) red[tid >> 5] = v;
        __syncthreads();
        if (tid == 0) {
            float n = red[0] + red[1] + red[2] + red[3];
            red[8] = n / (1.0f + n) * rsqrtf(n + EPSQ);
        }
        __syncthreads();
        if (tid < Hh) out[(size_t)bx * Hh + tid] = cap[tid] * red[8];
    }
}

// ---------------- launch -----------------------------------------------------
extern "C" void kernel_launch(void* const* d_in, const int* in_sizes, int n_in,
                              void* d_out, int out_size) {
    const float* item = (const float*)d_in[0];   // [B,S,H]
    const float* mask = (const float*)d_in[1];   // [B,S]
    const float* w    = (const float*)d_in[2];   // [1,S,K*H,H]
    float* out = (float*)d_out;                  // [B,K,H]

    cudaFuncSetAttribute(gemm_mma,
                         cudaFuncAttributeMaxDynamicSharedMemorySize, GEMM_SMEM);
    cudaFuncSetAttribute(routing01,
                         cudaFuncAttributeMaxDynamicSharedMemorySize, R01_SMEM);

    zero_dacc<<<1, 1024>>>();

    dim3 gg(Kk, Bb / 128, Ss);                   // (capsule, b-block, s)
    gemm_mma<<<gg, 256, GEMM_SMEM>>>(item, w);

    routing01<<<Bb * Kk, 256, R01_SMEM>>>(mask, 0);
    routing01<<<Bb * Kk, 256, R01_SMEM>>>(mask, 1);
    routing_final<<<Bb * Kk, 256>>>(mask, out);
}

// round 13
// speedup vs baseline: 3.8104x; 1.1171x over previous
#include <cuda_runtime.h>
#include <cuda_fp16.h>
#include <cstdint>

#define Bb 512
#define Ss 128
#define Kk 4
#define Hh 128
#define KH 512
#define EPSQ 1e-9f

typedef unsigned long long u64;

// ---------------- scratch (device globals; no allocation allowed) ----------
__device__ __half g_hat_h[(size_t)Bb * Kk * Ss * Hh];  // 67 MB fp16 hat
__device__ __half g_wh[(size_t)Ss * KH * Hh];          // 16.7 MB w hi
__device__ __half g_wl[(size_t)Ss * KH * Hh];          // 16.7 MB w lo
__device__ __half g_ih[(size_t)Bb * Ss * Hh];          // 16.7 MB item hi
__device__ __half g_il[(size_t)Bb * Ss * Hh];          // 16.7 MB item lo
__device__ float  g_cw  [(size_t)Bb * Kk * Ss];        // capsule_weight
__device__ float  g_dacc[2][Kk * Ss];                  // softmax denominators

// ---------------- mma / async helpers (generic PTX, compute_103-safe) -------
__device__ __forceinline__ void ldsm4(uint32_t* r, uint32_t addr) {
    asm volatile("ldmatrix.sync.aligned.m8n8.x4.shared.b16 {%0,%1,%2,%3}, [%4];"
                 : "=r"(r[0]), "=r"(r[1]), "=r"(r[2]), "=r"(r[3]) : "r"(addr));
}
__device__ __forceinline__ void mma16816(float* d, const uint32_t* a,
                                         uint32_t b0, uint32_t b1) {
    asm volatile(
        "mma.sync.aligned.m16n8k16.row.col.f32.f16.f16.f32 "
        "{%0,%1,%2,%3}, {%4,%5,%6,%7}, {%8,%9}, {%0,%1,%2,%3};"
        : "+f"(d[0]), "+f"(d[1]), "+f"(d[2]), "+f"(d[3])
        : "r"(a[0]), "r"(a[1]), "r"(a[2]), "r"(a[3]), "r"(b0), "r"(b1));
}
__device__ __forceinline__ void cpa16(uint32_t dst, const void* src) {
    asm volatile("cp.async.cg.shared.global [%0], [%1], 16;"
                 :: "r"(dst), "l"(src) : "memory");
}
__device__ __forceinline__ void cpa_wait_all() {
    asm volatile("cp.async.commit_group;\n\tcp.async.wait_group 0;" ::: "memory");
}

// ---------------- pre-split: fp32 -> fp16 hi/lo (w and item) ----------------
// grid (8192, 2) x 256: y=0 -> w (8.4M floats), y=1 -> item (8.4M floats)
__global__ void __launch_bounds__(256) presplit(const float* __restrict__ w,
                                                const float* __restrict__ item) {
    const size_t i4 = (size_t)blockIdx.x * 256 + threadIdx.x;   // float4 index
    const float4* src = (blockIdx.y == 0) ? (const float4*)w : (const float4*)item;
    __half* dh = (blockIdx.y == 0) ? g_wh : g_ih;
    __half* dl = (blockIdx.y == 0) ? g_wl : g_il;

    float4 v = src[i4];
    __half2 h0 = __floats2half2_rn(v.x, v.y);
    __half2 h1 = __floats2half2_rn(v.z, v.w);
    float2 f0 = __half22float2(h0), f1 = __half22float2(h1);
    __half2 l0 = __floats2half2_rn(v.x - f0.x, v.y - f0.y);
    __half2 l1 = __floats2half2_rn(v.z - f1.x, v.w - f1.y);
    uint2 hu, lu;
    hu.x = *(uint32_t*)&h0; hu.y = *(uint32_t*)&h1;
    lu.x = *(uint32_t*)&l0; lu.y = *(uint32_t*)&l1;
    *(uint2*)(dh + i4 * 4) = hu;
    *(uint2*)(dl + i4 * 4) = lu;

    if (blockIdx.x == 0 && blockIdx.y == 0) {
        #pragma unroll
        for (int j = 0; j < 4; j++)
            ((float*)g_dacc)[threadIdx.x + 256 * j] = 0.0f;
    }
}

// ---------------- fp16 3-term tensor-core GEMM -------------------------------
// hat[b,kcap,s,h] = sum_k item[b,s,k] * w[s, kcap*H+h, k]
// A = w rows (M=128), B = item rows (N=128), K=128 in 2 chunks of 64.
// smem per chunk: Ah, Al, Bh, Bl each [128 rows][64 fp16] = 16KB -> 64KB.
#define GEMM_SMEM 65536

__global__ void __launch_bounds__(256, 2) gemm_mma() {
    extern __shared__ char smc[];
    const uint32_t sb = (uint32_t)__cvta_generic_to_shared(smc);

    const int tid  = threadIdx.x;
    const int warp = tid >> 5, lane = tid & 31;
    const int kcap = blockIdx.x;
    const int d0   = kcap * 128;
    const int b0   = blockIdx.y * 128;
    const int s    = blockIdx.z;

    const int wm = warp & 1;             // m half (64 rows = 4 m16 tiles)
    const int wn = warp >> 1;            // n quarter (32 = 4 n8 tiles)
    const int m_base = wm * 64;
    const int n_base = wn * 32;

    const __half* Agh = g_wh + ((size_t)s * KH + d0) * Hh;
    const __half* Agl = g_wl + ((size_t)s * KH + d0) * Hh;
    const __half* Bgh = g_ih + ((size_t)b0 * Ss + s) * Hh;
    const __half* Bgl = g_il + ((size_t)b0 * Ss + s) * Hh;

    // ldmatrix lane geometry
    const int q = lane >> 3, rr = lane & 7;
    const int qa = q >> 1;                       // A k-unit low bit
    uint32_t baseA[4]; int m7A[4];
    #pragma unroll
    for (int mt = 0; mt < 4; mt++) {
        const int m = m_base + mt * 16 + ((q & 1) << 3) + rr;
        baseA[mt] = sb + (uint32_t)(m * 128);
        m7A[mt]   = m & 7;
    }
    const int qb = q & 1;                        // B k-unit low bit
    uint32_t baseB[2]; int n7B[2];
    #pragma unroll
    for (int nt2 = 0; nt2 < 2; nt2++) {
        const int n = n_base + nt2 * 16 + ((q >> 1) << 3) + rr;
        baseB[nt2] = sb + 32768u + (uint32_t)(n * 128);
        n7B[nt2]   = n & 7;
    }

    float acc[4][4][4];
    #pragma unroll
    for (int i = 0; i < 4; i++)
        #pragma unroll
        for (int j = 0; j < 4; j++)
            #pragma unroll
            for (int e = 0; e < 4; e++) acc[i][j][e] = 0.0f;

    const int u  = tid & 7;      // 16B unit within 128B chunk-row
    const int r0 = tid >> 3;     // 0..31

    #pragma unroll
    for (int c = 0; c < 2; c++) {
        __syncthreads();
        // ---- stage chunk c: pure cp.async copies (no cvt work)
        #pragma unroll
        for (int p = 0; p < 4; p++) {
            const int row = r0 + p * 32;
            const uint32_t so = (uint32_t)(row * 128) + ((uint32_t)(u ^ (row & 7)) << 4);
            const size_t aoff = (size_t)row * Hh + c * 64 + u * 8;
            const size_t boff = (size_t)row * (Ss * Hh) + c * 64 + u * 8;
            cpa16(sb + so,          Agh + aoff);    // Ah
            cpa16(sb + so + 16384,  Agl + aoff);    // Al
            cpa16(sb + so + 32768,  Bgh + boff);    // Bh
            cpa16(sb + so + 49152,  Bgl + boff);    // Bl
        }
        cpa_wait_all();
        __syncthreads();

        // ---- compute: 4 k16 steps, 3-term fp16 compensation
        #pragma unroll
        for (int kt = 0; kt < 4; kt++) {
            uint32_t bh[8], bl[8];
            #pragma unroll
            for (int nt2 = 0; nt2 < 2; nt2++) {
                const uint32_t ub = (uint32_t)((2 * kt + qb) ^ n7B[nt2]) << 4;
                ldsm4(&bh[nt2 * 4], baseB[nt2] + ub);
                ldsm4(&bl[nt2 * 4], baseB[nt2] + 16384u + ub);
            }
            #pragma unroll
            for (int mt = 0; mt < 4; mt++) {
                uint32_t ah[4], al[4];
                const uint32_t ua = (uint32_t)((2 * kt + qa) ^ m7A[mt]) << 4;
                ldsm4(ah, baseA[mt] + ua);
                ldsm4(al, baseA[mt] + 16384u + ua);
                #pragma unroll
                for (int nt = 0; nt < 4; nt++) {
                    mma16816(acc[mt][nt], ah, bl[nt * 2], bl[nt * 2 + 1]);
                    mma16816(acc[mt][nt], al, bh[nt * 2], bh[nt * 2 + 1]);
                    mma16816(acc[mt][nt], ah, bh[nt * 2], bh[nt * 2 + 1]);
                }
            }
        }
    }
    __syncthreads();

    // ---- epilogue: transpose to [n][m] fp16 (pitch 136), coalesced STG
    __half* smh = (__half*)smc;
    #pragma unroll
    for (int mt = 0; mt < 4; mt++) {
        #pragma unroll
        for (int nt = 0; nt < 4; nt++) {
            const int m = m_base + mt * 16 + (lane >> 2);
            const int n = n_base + nt * 8 + 2 * (lane & 3);
            smh[n * 136 + m]           = __float2half(acc[mt][nt][0]);
            smh[(n + 1) * 136 + m]     = __float2half(acc[mt][nt][1]);
            smh[n * 136 + m + 8]       = __float2half(acc[mt][nt][2]);
            smh[(n + 1) * 136 + m + 8] = __float2half(acc[mt][nt][3]);
        }
    }
    __syncthreads();
    #pragma unroll
    for (int i = tid; i < 2048; i += 256) {
        const int n = i >> 4, uo = i & 15;
        uint4 v = *(const uint4*)&smh[n * 136 + uo * 8];
        const int b = b0 + n;
        *(uint4*)&g_hat_h[(((size_t)b * Kk + kcap) * Ss + s) * Hh + uo * 8] = v;
    }
}

// ---------------- routing iters 0/1: fp16 hat, half2-vectorized -------------
#define HP2 68                              // padded half2 per s-row
#define R01_SMEM ((Ss * HP2) * 4 + (128 + 128 + 512) * 4)

__global__ void __launch_bounds__(256) routing01(const float* __restrict__ mask,
                                                 int iter) {
    extern __shared__ char smraw[];
    __half2* hat2 = (__half2*)smraw;                     // [128][HP2] = 34816B
    float*   sw   = (float*)(smraw + Ss * HP2 * 4);      // [128]
    float*   cap  = sw + 128;                            // [128]
    float*   red  = cap + 128;                           // [512]

    const int bx  = blockIdx.x;   // b*K + k
    const int b   = bx >> 2;
    const int k   = bx & 3;
    const int tid = threadIdx.x;

    // ---- stage fp16 tile into padded smem (uint4 = 4 half2 per op)
    {
        const uint4* src = (const uint4*)(g_hat_h + (size_t)bx * (Ss * Hh));
        #pragma unroll
        for (int i = 0; i < 8; i++) {
            int idx = tid + i * 256;           // 2048 uint4 total
            int s   = idx >> 4;
            int c4  = idx & 15;                // uint4 index within row
            *(uint4*)&hat2[s * HP2 + c4 * 4] = src[idx];
        }
    }

    // ---- sw[s]
    if (tid < Ss) {
        float m = mask[b * Ss + tid];
        float v;
        if (iter == 0) {
            v = 1.0f / (float)Bb;                       // softmax over b of zeros
        } else {
            float e = __expf(g_cw[(size_t)bx * Ss + tid]);
            v = e / g_dacc[0][k * Ss + tid];
        }
        sw[tid] = (m == 0.0f) ? 0.0f : v;
    }
    __syncthreads();

    // ---- cap: thread = (s-quarter, h2 pair); 32 half2 loads each
    {
        const int h2 = tid & 63, sq = tid >> 6;
        const __half2* hp = hat2 + sq * 32 * HP2 + h2;
        const float* sq_w = sw + sq * 32;
        float2 acc = make_float2(0.0f, 0.0f);
        #pragma unroll 8
        for (int j = 0; j < 32; j++) {
            float2 f = __half22float2(hp[j * HP2]);
            float  wv = sq_w[j];
            acc.x += wv * f.x;
            acc.y += wv * f.y;
        }
        *(float2*)&red[sq * 128 + 2 * h2] = acc;
    }
    __syncthreads();
    if (tid < Hh)
        cap[tid] = red[tid] + red[128 + tid] + red[256 + tid] + red[384 + tid];
    __syncthreads();

    // ---- squash
    {
        float v = (tid < Hh) ? cap[tid] * cap[tid] : 0.0f;
        #pragma unroll
        for (int off = 16; off; off >>= 1)
            v += __shfl_down_sync(0xffffffffu, v, off);
        if (tid < Hh && (tid & 31) == 0) red[tid >> 5] = v;
        __syncthreads();
        if (tid == 0) {
            float n = red[0] + red[1] + red[2] + red[3];
            red[8] = n / (1.0f + n) * rsqrtf(n + EPSQ);
        }
        __syncthreads();
        float f = red[8];
        if (tid < Hh) cap[tid] *= f;
    }
    __syncthreads();

    // ---- delta: 4 rows/warp/step via 8-lane groups; 3 xor-shfls to reduce
    {
        const int warp = tid >> 5, lane = tid & 31;
        const int g = lane >> 3, il = lane & 7;
        #pragma unroll
        for (int t = 0; t < 4; t++) {
            const int s = t * 32 + warp * 4 + g;
            const __half2* hp = hat2 + s * HP2;
            float d = 0.0f;
            #pragma unroll
            for (int j = 0; j < 8; j++) {
                const int c = il + 8 * j;
                float2 f = __half22float2(hp[c]);
                float2 cv = *(const float2*)&cap[2 * c];
                d += f.x * cv.x + f.y * cv.y;
            }
            d += __shfl_xor_sync(0xffffffffu, d, 4);
            d += __shfl_xor_sync(0xffffffffu, d, 2);
            d += __shfl_xor_sync(0xffffffffu, d, 1);
            if (il == 0) {
                size_t idx = (size_t)bx * Ss + s;
                float nc = (iter == 0) ? d : (g_cw[idx] + d);
                g_cw[idx] = nc;
                atomicAdd(&g_dacc[iter][k * Ss + s], __expf(nc));
            }
        }
    }
}

// ---------------- final iteration: fp16 stream, cap+squash+out only --------
__global__ void __launch_bounds__(256) routing_final(const float* __restrict__ mask,
                                                     float* __restrict__ out) {
    __shared__ float sw[Ss];
    __shared__ float cap[Hh];
    __shared__ float red[512];

    const int bx  = blockIdx.x;   // b*K + k
    const int b   = bx >> 2;
    const int k   = bx & 3;
    const int tid = threadIdx.x;

    if (tid < Ss) {
        float m = mask[b * Ss + tid];
        float e = __expf(g_cw[(size_t)bx * Ss + tid]);
        float v = e / g_dacc[1][k * Ss + tid];
        sw[tid] = (m == 0.0f) ? 0.0f : v;
    }
    __syncthreads();

    // cap partials straight from gmem (half2 columns, fully coalesced)
    {
        const int h2 = tid & 63, sq = tid >> 6;
        const __half2* hp = (const __half2*)g_hat_h
                          + (size_t)bx * (Ss * Hh / 2) + sq * 32 * 64 + h2;
        const float* sq_w = sw + sq * 32;
        float2 acc = make_float2(0.0f, 0.0f);
        #pragma unroll 8
        for (int j = 0; j < 32; j++) {
            float2 f = __half22float2(hp[j * 64]);
            float  wv = sq_w[j];
            acc.x += wv * f.x;
            acc.y += wv * f.y;
        }
        *(float2*)&red[sq * 128 + 2 * h2] = acc;
    }
    __syncthreads();
    if (tid < Hh)
        cap[tid] = red[tid] + red[128 + tid] + red[256 + tid] + red[384 + tid];
    __syncthreads();

    // squash + output
    {
        float v = (tid < Hh) ? cap[tid] * cap[tid] : 0.0f;
        #pragma unroll
        for (int off = 16; off; off >>= 1)
            v += __shfl_down_sync(0xffffffffu, v, off);
        if (tid < Hh && (tid & 31) == 0) red[tid >> 5] = v;
        __syncthreads();
        if (tid == 0) {
            float n = red[0] + red[1] + red[2] + red[3];
            red[8] = n / (1.0f + n) * rsqrtf(n + EPSQ);
        }
        __syncthreads();
        if (tid < Hh) out[(size_t)bx * Hh + tid] = cap[tid] * red[8];
    }
}

// ---------------- launch -----------------------------------------------------
extern "C" void kernel_launch(void* const* d_in, const int* in_sizes, int n_in,
                              void* d_out, int out_size) {
    const float* item = (const float*)d_in[0];   // [B,S,H]
    const float* mask = (const float*)d_in[1];   // [B,S]
    const float* w    = (const float*)d_in[2];   // [1,S,K*H,H]
    float* out = (float*)d_out;                  // [B,K,H]

    cudaFuncSetAttribute(gemm_mma,
                         cudaFuncAttributeMaxDynamicSharedMemorySize, GEMM_SMEM);
    cudaFuncSetAttribute(routing01,
                         cudaFuncAttributeMaxDynamicSharedMemorySize, R01_SMEM);

    presplit<<<dim3(8192, 2), 256>>>(w, item);   // also zeroes g_dacc

    dim3 gg(Kk, Bb / 128, Ss);                   // (capsule, b-block, s)
    gemm_mma<<<gg, 256, GEMM_SMEM>>>();

    routing01<<<Bb * Kk, 256, R01_SMEM>>>(mask, 0);
    routing01<<<Bb * Kk, 256, R01_SMEM>>>(mask, 1);
    routing_final<<<Bb * Kk, 256>>>(mask, out);
}

// round 14
// speedup vs baseline: 5.4298x; 1.4250x over previous
#include <cuda_runtime.h>
#include <cuda_fp16.h>
#include <cstdint>

#define Bb 512
#define Ss 128
#define Kk 4
#define Hh 128
#define KH 512
#define EPSQ 1e-9f

typedef unsigned long long u64;

// ---------------- scratch (device globals; no allocation allowed) ----------
__device__ __half g_hat_h[(size_t)Bb * Kk * Ss * Hh];  // 67 MB fp16 hat
__device__ __half g_wh[(size_t)Ss * KH * Hh];          // 16.7 MB w fp16
__device__ __half g_ih[(size_t)Bb * Ss * Hh];          // 16.7 MB item fp16
__device__ float  g_cw  [(size_t)Bb * Kk * Ss];        // capsule_weight
__device__ float  g_dacc[2][Kk * Ss];                  // softmax denominators

// ---------------- mma / async helpers (generic PTX, compute_103-safe) -------
__device__ __forceinline__ void ldsm4(uint32_t* r, uint32_t addr) {
    asm volatile("ldmatrix.sync.aligned.m8n8.x4.shared.b16 {%0,%1,%2,%3}, [%4];"
                 : "=r"(r[0]), "=r"(r[1]), "=r"(r[2]), "=r"(r[3]) : "r"(addr));
}
__device__ __forceinline__ void mma16816(float* d, const uint32_t* a,
                                         uint32_t b0, uint32_t b1) {
    asm volatile(
        "mma.sync.aligned.m16n8k16.row.col.f32.f16.f16.f32 "
        "{%0,%1,%2,%3}, {%4,%5,%6,%7}, {%8,%9}, {%0,%1,%2,%3};"
        : "+f"(d[0]), "+f"(d[1]), "+f"(d[2]), "+f"(d[3])
        : "r"(a[0]), "r"(a[1]), "r"(a[2]), "r"(a[3]), "r"(b0), "r"(b1));
}
__device__ __forceinline__ void cpa16(uint32_t dst, const void* src) {
    asm volatile("cp.async.cg.shared.global [%0], [%1], 16;"
                 :: "r"(dst), "l"(src) : "memory");
}
__device__ __forceinline__ void cpa_wait_all() {
    asm volatile("cp.async.commit_group;\n\tcp.async.wait_group 0;" ::: "memory");
}

// ---------------- pre-convert: fp32 -> fp16 (w and item) --------------------
// grid (8192, 2) x 256: y=0 -> w, y=1 -> item (8.39M floats each)
__global__ void __launch_bounds__(256) presplit(const float* __restrict__ w,
                                                const float* __restrict__ item) {
    const size_t i4 = (size_t)blockIdx.x * 256 + threadIdx.x;   // float4 index
    const float4* src = (blockIdx.y == 0) ? (const float4*)w : (const float4*)item;
    __half* dh = (blockIdx.y == 0) ? g_wh : g_ih;

    float4 v = src[i4];
    __half2 h0 = __floats2half2_rn(v.x, v.y);
    __half2 h1 = __floats2half2_rn(v.z, v.w);
    uint2 hu;
    hu.x = *(uint32_t*)&h0; hu.y = *(uint32_t*)&h1;
    *(uint2*)(dh + i4 * 4) = hu;

    if (blockIdx.x == 0 && blockIdx.y == 0) {
        #pragma unroll
        for (int j = 0; j < 4; j++)
            ((float*)g_dacc)[threadIdx.x + 256 * j] = 0.0f;
    }
}

// ---------------- fp16 tensor-core GEMM (single K=128 stage) -----------------
// hat[b,kcap,s,h] = sum_k item[b,s,k] * w[s, kcap*H+h, k]
// A = w rows (M=128), B = item rows (N=128). Tiles [128 x 128] fp16 = 32KB each.
#define GEMM_SMEM 65536

__global__ void __launch_bounds__(256, 2) gemm_mma() {
    extern __shared__ char smc[];
    const uint32_t sb = (uint32_t)__cvta_generic_to_shared(smc);

    const int tid  = threadIdx.x;
    const int warp = tid >> 5, lane = tid & 31;
    const int kcap = blockIdx.x;
    const int d0   = kcap * 128;
    const int b0   = blockIdx.y * 128;
    const int s    = blockIdx.z;

    const int wm = warp & 1;             // m half (64 rows = 4 m16 tiles)
    const int wn = warp >> 1;            // n quarter (32 = 4 n8 tiles)
    const int m_base = wm * 64;
    const int n_base = wn * 32;

    const __half* Agh = g_wh + ((size_t)s * KH + d0) * Hh;
    const __half* Bgh = g_ih + ((size_t)b0 * Ss + s) * Hh;

    // ldmatrix lane geometry (row pitch = 256B)
    const int q = lane >> 3, rr = lane & 7;
    const int qa = q >> 1;                       // A k-unit low bit
    uint32_t baseA[4]; int m7A[4];
    #pragma unroll
    for (int mt = 0; mt < 4; mt++) {
        const int m = m_base + mt * 16 + ((q & 1) << 3) + rr;
        baseA[mt] = sb + (uint32_t)(m * 256);
        m7A[mt]   = m & 7;
    }
    const int qb = q & 1;                        // B k-unit low bit
    uint32_t baseB[2]; int n7B[2];
    #pragma unroll
    for (int nt2 = 0; nt2 < 2; nt2++) {
        const int n = n_base + nt2 * 16 + ((q >> 1) << 3) + rr;
        baseB[nt2] = sb + 32768u + (uint32_t)(n * 256);
        n7B[nt2]   = n & 7;
    }

    float acc[4][4][4];
    #pragma unroll
    for (int i = 0; i < 4; i++)
        #pragma unroll
        for (int j = 0; j < 4; j++)
            #pragma unroll
            for (int e = 0; e < 4; e++) acc[i][j][e] = 0.0f;

    // ---- stage full K=128: pure cp.async (u = 16B unit 0..15, r0 = 0..15)
    const int u  = tid & 15;
    const int r0 = tid >> 4;
    #pragma unroll
    for (int p = 0; p < 8; p++) {
        const int row = r0 + p * 16;
        const uint32_t so = (uint32_t)(row * 256) + ((uint32_t)(u ^ (row & 7)) << 4);
        cpa16(sb + so,          Agh + (size_t)row * Hh + u * 8);
        cpa16(sb + 32768u + so, Bgh + (size_t)row * (Ss * Hh) + u * 8);
    }
    cpa_wait_all();
    __syncthreads();

    // ---- compute: 8 k16 steps, plain fp16 mma
    #pragma unroll
    for (int kt = 0; kt < 8; kt++) {
        uint32_t bh[8];
        #pragma unroll
        for (int nt2 = 0; nt2 < 2; nt2++) {
            const uint32_t ub = (uint32_t)((2 * kt + qb) ^ n7B[nt2]) << 4;
            ldsm4(&bh[nt2 * 4], baseB[nt2] + ub);
        }
        #pragma unroll
        for (int mt = 0; mt < 4; mt++) {
            uint32_t ah[4];
            const uint32_t ua = (uint32_t)((2 * kt + qa) ^ m7A[mt]) << 4;
            ldsm4(ah, baseA[mt] + ua);
            #pragma unroll
            for (int nt = 0; nt < 4; nt++)
                mma16816(acc[mt][nt], ah, bh[nt * 2], bh[nt * 2 + 1]);
        }
    }
    __syncthreads();

    // ---- epilogue: transpose to [n][m] fp16 (pitch 136), coalesced STG
    __half* smh = (__half*)smc;
    #pragma unroll
    for (int mt = 0; mt < 4; mt++) {
        #pragma unroll
        for (int nt = 0; nt < 4; nt++) {
            const int m = m_base + mt * 16 + (lane >> 2);
            const int n = n_base + nt * 8 + 2 * (lane & 3);
            smh[n * 136 + m]           = __float2half(acc[mt][nt][0]);
            smh[(n + 1) * 136 + m]     = __float2half(acc[mt][nt][1]);
            smh[n * 136 + m + 8]       = __float2half(acc[mt][nt][2]);
            smh[(n + 1) * 136 + m + 8] = __float2half(acc[mt][nt][3]);
        }
    }
    __syncthreads();
    #pragma unroll
    for (int i = tid; i < 2048; i += 256) {
        const int n = i >> 4, uo = i & 15;
        uint4 v = *(const uint4*)&smh[n * 136 + uo * 8];
        const int b = b0 + n;
        *(uint4*)&g_hat_h[(((size_t)b * Kk + kcap) * Ss + s) * Hh + uo * 8] = v;
    }
}

// ---------------- routing iters 0/1: fp16 hat, uint2-vectorized -------------
#define HP2 68                              // padded half2 per s-row
#define R01_SMEM ((Ss * HP2) * 4 + (128 + 128 + 1024) * 4)

__global__ void __launch_bounds__(256) routing01(const float* __restrict__ mask,
                                                 int iter) {
    extern __shared__ char smraw[];
    __half2* hat2 = (__half2*)smraw;                     // [128][HP2] = 34816B
    float*   sw   = (float*)(smraw + Ss * HP2 * 4);      // [128]
    float*   cap  = sw + 128;                            // [128]
    float*   red  = cap + 128;                           // [1024]

    const int bx  = blockIdx.x;   // b*K + k
    const int b   = bx >> 2;
    const int k   = bx & 3;
    const int tid = threadIdx.x;

    // ---- stage fp16 tile into padded smem (uint4 = 4 half2 per op)
    {
        const uint4* src = (const uint4*)(g_hat_h + (size_t)bx * (Ss * Hh));
        #pragma unroll
        for (int i = 0; i < 8; i++) {
            int idx = tid + i * 256;           // 2048 uint4 total
            int s   = idx >> 4;
            int c4  = idx & 15;                // uint4 index within row
            *(uint4*)&hat2[s * HP2 + c4 * 4] = src[idx];
        }
    }

    // ---- sw[s]
    if (tid < Ss) {
        float m = mask[b * Ss + tid];
        float v;
        if (iter == 0) {
            v = 1.0f / (float)Bb;                       // softmax over b of zeros
        } else {
            float e = __expf(g_cw[(size_t)bx * Ss + tid]);
            v = e / g_dacc[0][k * Ss + tid];
        }
        sw[tid] = (m == 0.0f) ? 0.0f : v;
    }
    __syncthreads();

    // ---- cap: thread = (row-group of 16, uint2 col = 4 h); fp32 accum
    {
        const int u2c = tid & 31, wg = tid >> 5;
        float4 acc = make_float4(0.f, 0.f, 0.f, 0.f);
        #pragma unroll
        for (int j = 0; j < 16; j++) {
            const int row = wg * 16 + j;
            uint2 v = *(const uint2*)&hat2[row * HP2 + u2c * 2];
            float wv = sw[row];
            float2 f0 = __half22float2(*(__half2*)&v.x);
            float2 f1 = __half22float2(*(__half2*)&v.y);
            acc.x += wv * f0.x; acc.y += wv * f0.y;
            acc.z += wv * f1.x; acc.w += wv * f1.y;
        }
        *(float4*)&red[wg * 128 + u2c * 4] = acc;
    }
    __syncthreads();
    if (tid < Hh) {
        float c = 0.0f;
        #pragma unroll
        for (int g = 0; g < 8; g++) c += red[g * 128 + tid];
        cap[tid] = c;
    }
    __syncthreads();

    // ---- squash
    {
        float v = (tid < Hh) ? cap[tid] * cap[tid] : 0.0f;
        #pragma unroll
        for (int off = 16; off; off >>= 1)
            v += __shfl_down_sync(0xffffffffu, v, off);
        if (tid < Hh && (tid & 31) == 0) red[tid >> 5] = v;
        __syncthreads();
        if (tid == 0) {
            float n = red[0] + red[1] + red[2] + red[3];
            red[8] = n / (1.0f + n) * rsqrtf(n + EPSQ);
        }
        __syncthreads();
        float f = red[8];
        if (tid < Hh) cap[tid] *= f;
    }
    __syncthreads();

    // ---- delta: 4 rows/warp/step via 8-lane groups; 3 xor-shfls to reduce
    {
        const int warp = tid >> 5, lane = tid & 31;
        const int g = lane >> 3, il = lane & 7;
        #pragma unroll
        for (int t = 0; t < 4; t++) {
            const int s = t * 32 + warp * 4 + g;
            const __half2* hp = hat2 + s * HP2;
            float d = 0.0f;
            #pragma unroll
            for (int j = 0; j < 8; j++) {
                const int c = il + 8 * j;
                float2 f = __half22float2(hp[c]);
                float2 cv = *(const float2*)&cap[2 * c];
                d += f.x * cv.x + f.y * cv.y;
            }
            d += __shfl_xor_sync(0xffffffffu, d, 4);
            d += __shfl_xor_sync(0xffffffffu, d, 2);
            d += __shfl_xor_sync(0xffffffffu, d, 1);
            if (il == 0) {
                size_t idx = (size_t)bx * Ss + s;
                float nc = (iter == 0) ? d : (g_cw[idx] + d);
                g_cw[idx] = nc;
                atomicAdd(&g_dacc[iter][k * Ss + s], __expf(nc));
            }
        }
    }
}

// ---------------- final iteration: fp16 stream, cap+squash+out only --------
__global__ void __launch_bounds__(256) routing_final(const float* __restrict__ mask,
                                                     float* __restrict__ out) {
    __shared__ float sw[Ss];
    __shared__ float cap[Hh];
    __shared__ float red[1024];

    const int bx  = blockIdx.x;   // b*K + k
    const int b   = bx >> 2;
    const int k   = bx & 3;
    const int tid = threadIdx.x;

    if (tid < Ss) {
        float m = mask[b * Ss + tid];
        float e = __expf(g_cw[(size_t)bx * Ss + tid]);
        float v = e / g_dacc[1][k * Ss + tid];
        sw[tid] = (m == 0.0f) ? 0.0f : v;
    }
    __syncthreads();

    // cap partials straight from gmem (uint2 = 4 h per load, coalesced)
    {
        const int u2c = tid & 31, wg = tid >> 5;
        const uint2* hp = (const uint2*)(g_hat_h + (size_t)bx * (Ss * Hh));
        float4 acc = make_float4(0.f, 0.f, 0.f, 0.f);
        #pragma unroll
        for (int j = 0; j < 16; j++) {
            const int row = wg * 16 + j;
            uint2 v = hp[row * 32 + u2c];
            float wv = sw[row];
            float2 f0 = __half22float2(*(__half2*)&v.x);
            float2 f1 = __half22float2(*(__half2*)&v.y);
            acc.x += wv * f0.x; acc.y += wv * f0.y;
            acc.z += wv * f1.x; acc.w += wv * f1.y;
        }
        *(float4*)&red[wg * 128 + u2c * 4] = acc;
    }
    __syncthreads();
    if (tid < Hh) {
        float c = 0.0f;
        #pragma unroll
        for (int g = 0; g < 8; g++) c += red[g * 128 + tid];
        cap[tid] = c;
    }
    __syncthreads();

    // squash + output
    {
        float v = (tid < Hh) ? cap[tid] * cap[tid] : 0.0f;
        #pragma unroll
        for (int off = 16; off; off >>= 1)
            v += __shfl_down_sync(0xffffffffu, v, off);
        if (tid < Hh && (tid & 31) == 0) red[tid >> 5] = v;
        __syncthreads();
        if (tid == 0) {
            float n = red[0] + red[1] + red[2] + red[3];
            red[8] = n / (1.0f + n) * rsqrtf(n + EPSQ);
        }
        __syncthreads();
        if (tid < Hh) out[(size_t)bx * Hh + tid] = cap[tid] * red[8];
    }
}

// ---------------- launch -----------------------------------------------------
extern "C" void kernel_launch(void* const* d_in, const int* in_sizes, int n_in,
                              void* d_out, int out_size) {
    const float* item = (const float*)d_in[0];   // [B,S,H]
    const float* mask = (const float*)d_in[1];   // [B,S]
    const float* w    = (const float*)d_in[2];   // [1,S,K*H,H]
    float* out = (float*)d_out;                  // [B,K,H]

    cudaFuncSetAttribute(gemm_mma,
                         cudaFuncAttributeMaxDynamicSharedMemorySize, GEMM_SMEM);
    cudaFuncSetAttribute(routing01,
                         cudaFuncAttributeMaxDynamicSharedMemorySize, R01_SMEM);

    presplit<<<dim3(8192, 2), 256>>>(w, item);   // also zeroes g_dacc

    dim3 gg(Kk, Bb / 128, Ss);                   // (capsule, b-block, s)
    gemm_mma<<<gg, 256, GEMM_SMEM>>>();

    routing01<<<Bb * Kk, 256, R01_SMEM>>>(mask, 0);
    routing01<<<Bb * Kk, 256, R01_SMEM>>>(mask, 1);
    routing_final<<<Bb * Kk, 256>>>(mask, out);
}

// round 15
// speedup vs baseline: 5.4436x; 1.0025x over previous
#include <cuda_runtime.h>
#include <cuda_fp16.h>
#include <cstdint>

#define Bb 512
#define Ss 128
#define Kk 4
#define Hh 128
#define KH 512
#define EPSQ 1e-9f

typedef unsigned long long u64;

// ---------------- scratch (device globals; no allocation allowed) ----------
__device__ __half g_hat_h[(size_t)Bb * Kk * Ss * Hh];  // 67 MB fp16 hat
__device__ __half g_wh[(size_t)Ss * KH * Hh];          // 16.7 MB w fp16
__device__ __half g_ih[(size_t)Bb * Ss * Hh];          // 16.7 MB item fp16
__device__ float  g_cw  [(size_t)Bb * Kk * Ss];        // capsule_weight
__device__ float  g_dacc[2][Kk * Ss];                  // softmax denominators

// ---------------- mma / async helpers (generic PTX, compute_103-safe) -------
__device__ __forceinline__ void ldsm4(uint32_t* r, uint32_t addr) {
    asm volatile("ldmatrix.sync.aligned.m8n8.x4.shared.b16 {%0,%1,%2,%3}, [%4];"
                 : "=r"(r[0]), "=r"(r[1]), "=r"(r[2]), "=r"(r[3]) : "r"(addr));
}
__device__ __forceinline__ void mma16816(float* d, const uint32_t* a,
                                         uint32_t b0, uint32_t b1) {
    asm volatile(
        "mma.sync.aligned.m16n8k16.row.col.f32.f16.f16.f32 "
        "{%0,%1,%2,%3}, {%4,%5,%6,%7}, {%8,%9}, {%0,%1,%2,%3};"
        : "+f"(d[0]), "+f"(d[1]), "+f"(d[2]), "+f"(d[3])
        : "r"(a[0]), "r"(a[1]), "r"(a[2]), "r"(a[3]), "r"(b0), "r"(b1));
}
__device__ __forceinline__ void cpa16(uint32_t dst, const void* src) {
    asm volatile("cp.async.cg.shared.global [%0], [%1], 16;"
                 :: "r"(dst), "l"(src) : "memory");
}
__device__ __forceinline__ void cpa_wait_all() {
    asm volatile("cp.async.commit_group;\n\tcp.async.wait_group 0;" ::: "memory");
}

// ---------------- pre-convert: fp32 -> fp16 (w and item) --------------------
// grid (8192, 2) x 256: y=0 -> w, y=1 -> item (8.39M floats each)
__global__ void __launch_bounds__(256) presplit(const float* __restrict__ w,
                                                const float* __restrict__ item) {
    const size_t i4 = (size_t)blockIdx.x * 256 + threadIdx.x;   // float4 index
    const float4* src = (blockIdx.y == 0) ? (const float4*)w : (const float4*)item;
    __half* dh = (blockIdx.y == 0) ? g_wh : g_ih;

    float4 v = src[i4];
    __half2 h0 = __floats2half2_rn(v.x, v.y);
    __half2 h1 = __floats2half2_rn(v.z, v.w);
    uint2 hu;
    hu.x = *(uint32_t*)&h0; hu.y = *(uint32_t*)&h1;
    *(uint2*)(dh + i4 * 4) = hu;

    if (blockIdx.x == 0 && blockIdx.y == 0) {
        #pragma unroll
        for (int j = 0; j < 4; j++)
            ((float*)g_dacc)[threadIdx.x + 256 * j] = 0.0f;
    }
}

// ---------------- fp16 tensor-core GEMM (single K=128 stage) -----------------
// hat[b,kcap,s,h] = sum_k item[b,s,k] * w[s, kcap*H+h, k]
// A = w rows (M=128), B = item rows (N=128). Tiles [128 x 128] fp16 = 32KB each.
#define GEMM_SMEM 65536

__global__ void __launch_bounds__(256, 2) gemm_mma() {
    extern __shared__ char smc[];
    const uint32_t sb = (uint32_t)__cvta_generic_to_shared(smc);

    const int tid  = threadIdx.x;
    const int warp = tid >> 5, lane = tid & 31;
    const int kcap = blockIdx.x;
    const int d0   = kcap * 128;
    const int b0   = blockIdx.y * 128;
    const int s    = blockIdx.z;

    const int wm = warp & 1;             // m half (64 rows = 4 m16 tiles)
    const int wn = warp >> 1;            // n quarter (32 = 4 n8 tiles)
    const int m_base = wm * 64;
    const int n_base = wn * 32;

    const __half* Agh = g_wh + ((size_t)s * KH + d0) * Hh;
    const __half* Bgh = g_ih + ((size_t)b0 * Ss + s) * Hh;

    // ldmatrix lane geometry (row pitch = 256B)
    const int q = lane >> 3, rr = lane & 7;
    const int qa = q >> 1;                       // A k-unit low bit
    uint32_t baseA[4]; int m7A[4];
    #pragma unroll
    for (int mt = 0; mt < 4; mt++) {
        const int m = m_base + mt * 16 + ((q & 1) << 3) + rr;
        baseA[mt] = sb + (uint32_t)(m * 256);
        m7A[mt]   = m & 7;
    }
    const int qb = q & 1;                        // B k-unit low bit
    uint32_t baseB[2]; int n7B[2];
    #pragma unroll
    for (int nt2 = 0; nt2 < 2; nt2++) {
        const int n = n_base + nt2 * 16 + ((q >> 1) << 3) + rr;
        baseB[nt2] = sb + 32768u + (uint32_t)(n * 256);
        n7B[nt2]   = n & 7;
    }

    float acc[4][4][4];
    #pragma unroll
    for (int i = 0; i < 4; i++)
        #pragma unroll
        for (int j = 0; j < 4; j++)
            #pragma unroll
            for (int e = 0; e < 4; e++) acc[i][j][e] = 0.0f;

    // ---- stage full K=128: pure cp.async (u = 16B unit 0..15, r0 = 0..15)
    const int u  = tid & 15;
    const int r0 = tid >> 4;
    #pragma unroll
    for (int p = 0; p < 8; p++) {
        const int row = r0 + p * 16;
        const uint32_t so = (uint32_t)(row * 256) + ((uint32_t)(u ^ (row & 7)) << 4);
        cpa16(sb + so,          Agh + (size_t)row * Hh + u * 8);
        cpa16(sb + 32768u + so, Bgh + (size_t)row * (Ss * Hh) + u * 8);
    }
    cpa_wait_all();
    __syncthreads();

    // ---- compute: 8 k16 steps, plain fp16 mma
    #pragma unroll
    for (int kt = 0; kt < 8; kt++) {
        uint32_t bh[8];
        #pragma unroll
        for (int nt2 = 0; nt2 < 2; nt2++) {
            const uint32_t ub = (uint32_t)((2 * kt + qb) ^ n7B[nt2]) << 4;
            ldsm4(&bh[nt2 * 4], baseB[nt2] + ub);
        }
        #pragma unroll
        for (int mt = 0; mt < 4; mt++) {
            uint32_t ah[4];
            const uint32_t ua = (uint32_t)((2 * kt + qa) ^ m7A[mt]) << 4;
            ldsm4(ah, baseA[mt] + ua);
            #pragma unroll
            for (int nt = 0; nt < 4; nt++)
                mma16816(acc[mt][nt], ah, bh[nt * 2], bh[nt * 2 + 1]);
        }
    }
    __syncthreads();

    // ---- epilogue: transpose to [n][m] fp16 (pitch 136), coalesced STG
    __half* smh = (__half*)smc;
    #pragma unroll
    for (int mt = 0; mt < 4; mt++) {
        #pragma unroll
        for (int nt = 0; nt < 4; nt++) {
            const int m = m_base + mt * 16 + (lane >> 2);
            const int n = n_base + nt * 8 + 2 * (lane & 3);
            smh[n * 136 + m]           = __float2half(acc[mt][nt][0]);
            smh[(n + 1) * 136 + m]     = __float2half(acc[mt][nt][1]);
            smh[n * 136 + m + 8]       = __float2half(acc[mt][nt][2]);
            smh[(n + 1) * 136 + m + 8] = __float2half(acc[mt][nt][3]);
        }
    }
    __syncthreads();
    #pragma unroll
    for (int i = tid; i < 2048; i += 256) {
        const int n = i >> 4, uo = i & 15;
        uint4 v = *(const uint4*)&smh[n * 136 + uo * 8];
        const int b = b0 + n;
        *(uint4*)&g_hat_h[(((size_t)b * Kk + kcap) * Ss + s) * Hh + uo * 8] = v;
    }
}

// ---------------- routing iters 0/1: fused stage+cap, fp16 hat --------------
#define HP2 68                              // padded half2 per s-row
#define R01_SMEM ((Ss * HP2) * 4 + (128 + 128 + 2048 + 16) * 4)

__global__ void __launch_bounds__(256) routing01(const float* __restrict__ mask,
                                                 int iter) {
    extern __shared__ char smraw[];
    __half2* hat2 = (__half2*)smraw;                     // [128][HP2] = 34816B
    float*   sw   = (float*)(smraw + Ss * HP2 * 4);      // [128]
    float*   cap  = sw + 128;                            // [128]
    float*   red  = cap + 128;                           // [2048]

    const int bx  = blockIdx.x;   // b*K + k
    const int b   = bx >> 2;
    const int k   = bx & 3;
    const int tid = threadIdx.x;
    const int c4  = tid & 15;     // fixed 8-half column group
    const int rg  = tid >> 4;     // base row 0..15

    // ---- issue hat loads early (MLP = 8, latency hidden behind sw)
    const uint4* src = (const uint4*)(g_hat_h + (size_t)bx * (Ss * Hh));
    uint4 v[8];
    #pragma unroll
    for (int i = 0; i < 8; i++) v[i] = src[tid + i * 256];

    // ---- sw[s]
    if (tid < Ss) {
        float m = mask[b * Ss + tid];
        float x;
        if (iter == 0) {
            x = 1.0f / (float)Bb;                       // softmax over b of zeros
        } else {
            float e = __expf(g_cw[(size_t)bx * Ss + tid]);
            x = e / g_dacc[0][k * Ss + tid];
        }
        sw[tid] = (m == 0.0f) ? 0.0f : x;
    }
    __syncthreads();

    // ---- fused: cap partials from registers + store tile for delta pass
    {
        float2 a0 = make_float2(0.f, 0.f), a1 = a0, a2 = a0, a3 = a0;
        #pragma unroll
        for (int i = 0; i < 8; i++) {
            const int row = rg + 16 * i;
            *(uint4*)&hat2[row * HP2 + c4 * 4] = v[i];
            const float wv = sw[row];
            float2 f;
            f = __half22float2(*(__half2*)&v[i].x); a0.x += wv * f.x; a0.y += wv * f.y;
            f = __half22float2(*(__half2*)&v[i].y); a1.x += wv * f.x; a1.y += wv * f.y;
            f = __half22float2(*(__half2*)&v[i].z); a2.x += wv * f.x; a2.y += wv * f.y;
            f = __half22float2(*(__half2*)&v[i].w); a3.x += wv * f.x; a3.y += wv * f.y;
        }
        *(float4*)&red[rg * 128 + c4 * 8]     = make_float4(a0.x, a0.y, a1.x, a1.y);
        *(float4*)&red[rg * 128 + c4 * 8 + 4] = make_float4(a2.x, a2.y, a3.x, a3.y);
    }
    __syncthreads();
    if (tid < Hh) {
        float c = 0.0f;
        #pragma unroll
        for (int g = 0; g < 16; g++) c += red[g * 128 + tid];
        cap[tid] = c;
    }
    __syncthreads();

    // ---- squash
    {
        float x = (tid < Hh) ? cap[tid] * cap[tid] : 0.0f;
        #pragma unroll
        for (int off = 16; off; off >>= 1)
            x += __shfl_down_sync(0xffffffffu, x, off);
        if (tid < Hh && (tid & 31) == 0) red[tid >> 5] = x;
        __syncthreads();
        if (tid == 0) {
            float n = red[0] + red[1] + red[2] + red[3];
            red[8] = n / (1.0f + n) * rsqrtf(n + EPSQ);
        }
        __syncthreads();
        float f = red[8];
        if (tid < Hh) cap[tid] *= f;
    }
    __syncthreads();

    // ---- delta: 4 rows/warp/step via 8-lane groups; 3 xor-shfls to reduce
    {
        const int warp = tid >> 5, lane = tid & 31;
        const int g = lane >> 3, il = lane & 7;
        #pragma unroll
        for (int t = 0; t < 4; t++) {
            const int s = t * 32 + warp * 4 + g;
            const __half2* hp = hat2 + s * HP2;
            float d = 0.0f;
            #pragma unroll
            for (int j = 0; j < 8; j++) {
                const int c = il + 8 * j;
                float2 f = __half22float2(hp[c]);
                float2 cv = *(const float2*)&cap[2 * c];
                d += f.x * cv.x + f.y * cv.y;
            }
            d += __shfl_xor_sync(0xffffffffu, d, 4);
            d += __shfl_xor_sync(0xffffffffu, d, 2);
            d += __shfl_xor_sync(0xffffffffu, d, 1);
            if (il == 0) {
                size_t idx = (size_t)bx * Ss + s;
                float nc = (iter == 0) ? d : (g_cw[idx] + d);
                g_cw[idx] = nc;
                atomicAdd(&g_dacc[iter][k * Ss + s], __expf(nc));
            }
        }
    }
}

// ---------------- final iteration: fused gmem cap, squash, out --------------
__global__ void __launch_bounds__(256) routing_final(const float* __restrict__ mask,
                                                     float* __restrict__ out) {
    __shared__ float sw[Ss];
    __shared__ float cap[Hh];
    __shared__ float red[2048];

    const int bx  = blockIdx.x;   // b*K + k
    const int b   = bx >> 2;
    const int k   = bx & 3;
    const int tid = threadIdx.x;
    const int c4  = tid & 15;
    const int rg  = tid >> 4;

    // ---- issue hat loads early
    const uint4* src = (const uint4*)(g_hat_h + (size_t)bx * (Ss * Hh));
    uint4 v[8];
    #pragma unroll
    for (int i = 0; i < 8; i++) v[i] = src[tid + i * 256];

    if (tid < Ss) {
        float m = mask[b * Ss + tid];
        float e = __expf(g_cw[(size_t)bx * Ss + tid]);
        float x = e / g_dacc[1][k * Ss + tid];
        sw[tid] = (m == 0.0f) ? 0.0f : x;
    }
    __syncthreads();

    // ---- cap partials from registers
    {
        float2 a0 = make_float2(0.f, 0.f), a1 = a0, a2 = a0, a3 = a0;
        #pragma unroll
        for (int i = 0; i < 8; i++) {
            const int row = rg + 16 * i;
            const float wv = sw[row];
            float2 f;
            f = __half22float2(*(__half2*)&v[i].x); a0.x += wv * f.x; a0.y += wv * f.y;
            f = __half22float2(*(__half2*)&v[i].y); a1.x += wv * f.x; a1.y += wv * f.y;
            f = __half22float2(*(__half2*)&v[i].z); a2.x += wv * f.x; a2.y += wv * f.y;
            f = __half22float2(*(__half2*)&v[i].w); a3.x += wv * f.x; a3.y += wv * f.y;
        }
        *(float4*)&red[rg * 128 + c4 * 8]     = make_float4(a0.x, a0.y, a1.x, a1.y);
        *(float4*)&red[rg * 128 + c4 * 8 + 4] = make_float4(a2.x, a2.y, a3.x, a3.y);
    }
    __syncthreads();
    if (tid < Hh) {
        float c = 0.0f;
        #pragma unroll
        for (int g = 0; g < 16; g++) c += red[g * 128 + tid];
        cap[tid] = c;
    }
    __syncthreads();

    // squash + output
    {
        float x = (tid < Hh) ? cap[tid] * cap[tid] : 0.0f;
        #pragma unroll
        for (int off = 16; off; off >>= 1)
            x += __shfl_down_sync(0xffffffffu, x, off);
        if (tid < Hh && (tid & 31) == 0) red[tid >> 5] = x;
        __syncthreads();
        if (tid == 0) {
            float n = red[0] + red[1] + red[2] + red[3];
            red[8] = n / (1.0f + n) * rsqrtf(n + EPSQ);
        }
        __syncthreads();
        if (tid < Hh) out[(size_t)bx * Hh + tid] = cap[tid] * red[8];
    }
}

// ---------------- launch -----------------------------------------------------
extern "C" void kernel_launch(void* const* d_in, const int* in_sizes, int n_in,
                              void* d_out, int out_size) {
    const float* item = (const float*)d_in[0];   // [B,S,H]
    const float* mask = (const float*)d_in[1];   // [B,S]
    const float* w    = (const float*)d_in[2];   // [1,S,K*H,H]
    float* out = (float*)d_out;                  // [B,K,H]

    cudaFuncSetAttribute(gemm_mma,
                         cudaFuncAttributeMaxDynamicSharedMemorySize, GEMM_SMEM);
    cudaFuncSetAttribute(routing01,
                         cudaFuncAttributeMaxDynamicSharedMemorySize, R01_SMEM);

    presplit<<<dim3(8192, 2), 256>>>(w, item);   // also zeroes g_dacc

    dim3 gg(Kk, Bb / 128, Ss);                   // (capsule, b-block, s)
    gemm_mma<<<gg, 256, GEMM_SMEM>>>();

    routing01<<<Bb * Kk, 256, R01_SMEM>>>(mask, 0);
    routing01<<<Bb * Kk, 256, R01_SMEM>>>(mask, 1);
    routing_final<<<Bb * Kk, 256>>>(mask, out);
}